// round 11
// baseline (speedup 1.0000x reference)
#include <cuda_runtime.h>
#include <cuda_fp16.h>
#include <math.h>
#include <stdint.h>

#define BB   32768
#define DD   1024
#define NHEAD 8
#define KTAP 4
#define EPSV 1e-6f
#define CAPV 15.0f

// ---------------- scratch (allocation-free, __device__ globals) ----------------
__device__ __half g_xh[(size_t)BB * DD];     // x as fp16
__device__ __half g_xch[(size_t)BB * DD];    // SiLU(conv tap) as fp16
__device__ __half g_hh[(size_t)BB * DD];     // h_norm as fp16
__device__ __half g_wc_hi[DD * DD];          // conv last tap
__device__ __half g_wz_hi[DD * DD];          // z_w
__device__ __half g_wo_hi[DD * DD];          // out_w
__device__ float g_it[BB * NHEAD];
__device__ float g_ft[BB * NHEAD];
__device__ float g_og[BB * NHEAD];

// ================= low-level helpers (arch-portable, sm_80+) ===================
__device__ __forceinline__ uint32_t smem_u32(const void* p) {
    uint32_t a;
    asm("{ .reg .u64 t; cvta.to.shared.u64 t, %1; cvt.u32.u64 %0, t; }" : "=r"(a) : "l"(p));
    return a;
}
__device__ __forceinline__ void cp16(uint32_t dst, const void* src) {
    asm volatile("cp.async.cg.shared.global [%0], [%1], 16;" :: "r"(dst), "l"(src));
}
__device__ __forceinline__ void cp_commit() {
    asm volatile("cp.async.commit_group;" ::: "memory");
}
__device__ __forceinline__ void cp_wait0() {
    asm volatile("cp.async.wait_group 0;" ::: "memory");
}
__device__ __forceinline__ void ldsm4(uint32_t* r, uint32_t addr) {
    asm volatile("ldmatrix.sync.aligned.m8n8.x4.shared.b16 {%0,%1,%2,%3}, [%4];"
                 : "=r"(r[0]), "=r"(r[1]), "=r"(r[2]), "=r"(r[3]) : "r"(addr));
}
__device__ __forceinline__ void mma_f16(float* d, const uint32_t* a, const uint32_t* b) {
    asm volatile(
        "mma.sync.aligned.m16n8k16.row.col.f32.f16.f16.f32 "
        "{%0,%1,%2,%3}, {%4,%5,%6,%7}, {%8,%9}, {%0,%1,%2,%3};"
        : "+f"(d[0]), "+f"(d[1]), "+f"(d[2]), "+f"(d[3])
        : "r"(a[0]), "r"(a[1]), "r"(a[2]), "r"(a[3]), "r"(b[0]), "r"(b[1]));
}

// ================= conversion kernels ==========================================
__global__ void tohalf_kernel(const float* __restrict__ in, __half* __restrict__ out, int n8) {
    int i = blockIdx.x * blockDim.x + threadIdx.x;
    if (i >= n8) return;
    float4 a = ((const float4*)in)[i * 2];
    float4 b = ((const float4*)in)[i * 2 + 1];
    __half2 h[4];
    h[0] = __floats2half2_rn(a.x, a.y);
    h[1] = __floats2half2_rn(a.z, a.w);
    h[2] = __floats2half2_rn(b.x, b.y);
    h[3] = __floats2half2_rn(b.z, b.w);
    ((uint4*)out)[i] = *(uint4*)h;
}

__global__ void wconv_kernel(const float* __restrict__ conv_w) {
    int i = blockIdx.x * blockDim.x + threadIdx.x;
    if (i >= DD * DD) return;
    g_wc_hi[i] = __float2half_rn(conv_w[(size_t)i * KTAP + (KTAP - 1)]);
}

// ================= tensor-core GEMM =============================================
// C[M,1024] = A[M,1024] * W[1024,1024]^T, fp16 operands, fp32 accum.
// Block 128x128, BK=64, 2 stages, one __syncthreads per k-iter, 2 CTAs/SM.
// MODE 0: fp32 out. MODE 1: SiLU(y+bias) -> fp16 out.
// MODE 2: fused sLSTM gating + per-head LayerNorm epilogue (tile = one head).
#define TSTRIDE   144                     // 128B data + 16B pad (conflict-free)
#define TENSOR_B  (128 * TSTRIDE)         // 18432
#define STAGE_B   (2 * TENSOR_B)          // Ah, Whi = 36864
#define NSTAGE    2
#define GEMM_SMEM (NSTAGE * STAGE_B)      // 73728

template <int MODE>
__global__ void __launch_bounds__(256, 2)
gemm2_kernel(const __half* __restrict__ Ah, const __half* __restrict__ Whi,
             const float* __restrict__ bias, void* __restrict__ Cout,
             const float* __restrict__ cc, const float* __restrict__ nn_,
             const float* __restrict__ mm_,
             const float* __restrict__ gw, const float* __restrict__ gb,
             float* __restrict__ c_out, float* __restrict__ n_out,
             float* __restrict__ m_out) {
    extern __shared__ char dynsmem[];
    const uint32_t sbase = smem_u32(dynsmem);

    const int t      = threadIdx.x;
    const int lane   = t & 31;
    const int wid    = t >> 5;
    const int warp_m = wid >> 2;
    const int warp_n = wid & 3;
    const int m0     = blockIdx.y * 128;
    const int n0     = blockIdx.x * 128;

    const char* srcs[2];
    srcs[0] = (const char*)(Ah  + (size_t)m0 * DD);
    srcs[1] = (const char*)(Whi + (size_t)n0 * DD);

    // 2048 16B chunks per stage (2 tensors x 128 rows x 8 chunks), 8 per thread
    int l_tensor[8], l_row[8], l_ch[8];
#pragma unroll
    for (int j = 0; j < 8; j++) {
        int cid = t + j * 256;
        l_tensor[j] = cid >> 10;
        int rc = cid & 1023;
        l_row[j] = rc >> 3;
        l_ch[j]  = rc & 7;
    }

    auto load_stage = [&](int stg, int kiter) {
        uint32_t sdst = sbase + stg * STAGE_B;
        int k0b = kiter * 128;                // 64 fp16 = 128B along K
#pragma unroll
        for (int j = 0; j < 8; j++) {
            uint32_t dst = sdst + l_tensor[j] * TENSOR_B + l_row[j] * TSTRIDE + l_ch[j] * 16;
            const char* src = srcs[l_tensor[j]] + (size_t)l_row[j] * 2048 + k0b + l_ch[j] * 16;
            cp16(dst, src);
        }
    };

    float acc[4][4][4];
#pragma unroll
    for (int i = 0; i < 4; i++)
#pragma unroll
        for (int j = 0; j < 4; j++)
#pragma unroll
            for (int q = 0; q < 4; q++) acc[i][j][q] = 0.0f;

    const uint32_t offA = (uint32_t)((warp_m * 64 + (lane & 15)) * TSTRIDE + (lane >> 4) * 16);
    const uint32_t offB = (uint32_t)((warp_n * 32 + ((lane >> 4) << 3) + (lane & 7)) * TSTRIDE
                        + (((lane >> 3) & 1) << 4));

    load_stage(0, 0);
    cp_commit();

    for (int i = 0; i < 16; i++) {
        cp_wait0();
        __syncthreads();
        if (i + 1 < 16) {
            load_stage((i + 1) & 1, i + 1);
            cp_commit();
        }
        const uint32_t stg = sbase + (i & 1) * STAGE_B;
#pragma unroll
        for (int k16 = 0; k16 < 4; k16++) {
            const uint32_t koff = k16 * 32;
            uint32_t bh[2][4];
#pragma unroll
            for (int p = 0; p < 2; p++)
                ldsm4(bh[p], stg + TENSOR_B + offB + p * (16 * TSTRIDE) + koff);
#pragma unroll
            for (int mt = 0; mt < 4; mt++) {
                uint32_t ah[4];
                ldsm4(ah, stg + offA + mt * (16 * TSTRIDE) + koff);
#pragma unroll
                for (int nt = 0; nt < 4; nt++)
                    mma_f16(acc[mt][nt], ah, &bh[nt >> 1][(nt & 1) * 2]);
            }
        }
    }

    const int g  = lane >> 2;
    const int tg = lane & 3;

    if (MODE == 2) {
        // ======== fused gating + per-head LayerNorm epilogue ====================
        const int hidx = blockIdx.x;   // tile n-range == head hidx
        float* ep    = (float*)dynsmem;
        float* sig   = ep;            // [128] i gate (exp)
        float* sfg   = ep + 128;      // [128] f gate (exp)
        float* sog   = ep + 256;      // [128] o gate (sigmoid)
        float* gwsm  = ep + 384;      // [128]
        float* gbsm  = ep + 512;      // [128]
        float* rsum  = ep + 640;      // [4][128]
        float* rsq   = ep + 1152;     // [4][128]

        __syncthreads();              // mainloop smem dead
        if (t < 128) {
            int bh_i = (m0 + t) * 8 + hidx;
            float it  = g_it[bh_i];
            float ft  = g_ft[bh_i];
            float m0v = mm_[bh_i];
            float fl  = -log1pf(expf(-ft));
            float mn  = fmaxf(fl + m0v, it);
            sig[t] = expf(it - mn);
            sfg[t] = expf(fl + m0v - mn);
            sog[t] = g_og[bh_i];
            m_out[bh_i] = mn;
        } else {
            int e = t - 128;
            gwsm[e] = gw[hidx * 128 + e];
            gbsm[e] = gb[hidx * 128 + e];
        }
        __syncthreads();

        // phase 1: c_new/n_new, h, partial row sums
#pragma unroll
        for (int mt = 0; mt < 4; mt++) {
#pragma unroll
            for (int hf = 0; hf < 2; hf++) {
                int r = warp_m * 64 + mt * 16 + g + hf * 8;
                float igv = sig[r], fgv = sfg[r], ogv = sog[r];
                size_t rowbase = (size_t)(m0 + r) * 1024 + hidx * 128;
                float s = 0.f, sq = 0.f;
#pragma unroll
                for (int nt = 0; nt < 4; nt++) {
                    int e = warp_n * 32 + nt * 8 + tg * 2;
                    float2 cv = *(const float2*)&cc[rowbase + e];
                    float2 nv = *(const float2*)&nn_[rowbase + e];
                    float z0 = acc[mt][nt][hf * 2 + 0];
                    float z1 = acc[mt][nt][hf * 2 + 1];
                    float cn0 = fgv * cv.x + igv * z0;
                    float cn1 = fgv * cv.y + igv * z1;
                    float nn0 = fgv * nv.x + igv;
                    float nn1 = fgv * nv.y + igv;
                    *(float2*)&c_out[rowbase + e] = make_float2(cn0, cn1);
                    *(float2*)&n_out[rowbase + e] = make_float2(nn0, nn1);
                    float h0 = ogv * cn0 / (nn0 + EPSV);
                    float h1 = ogv * cn1 / (nn1 + EPSV);
                    acc[mt][nt][hf * 2 + 0] = h0;
                    acc[mt][nt][hf * 2 + 1] = h1;
                    s += h0 + h1;
                    sq += h0 * h0 + h1 * h1;
                }
                s  += __shfl_xor_sync(0xffffffffu, s, 1);
                s  += __shfl_xor_sync(0xffffffffu, s, 2);
                sq += __shfl_xor_sync(0xffffffffu, sq, 1);
                sq += __shfl_xor_sync(0xffffffffu, sq, 2);
                if (tg == 0) {
                    rsum[warp_n * 128 + r] = s;
                    rsq[warp_n * 128 + r]  = sq;
                }
            }
        }
        __syncthreads();

        // phase 2: normalize + affine -> fp16 h
#pragma unroll
        for (int mt = 0; mt < 4; mt++) {
#pragma unroll
            for (int hf = 0; hf < 2; hf++) {
                int r = warp_m * 64 + mt * 16 + g + hf * 8;
                float s  = rsum[r] + rsum[128 + r] + rsum[256 + r] + rsum[384 + r];
                float sq = rsq[r]  + rsq[128 + r]  + rsq[256 + r]  + rsq[384 + r];
                float mu  = s * (1.0f / 128.0f);
                float var = sq * (1.0f / 128.0f) - mu * mu;
                float rs  = rsqrtf(var + EPSV);
                size_t rowbase = (size_t)(m0 + r) * 1024 + hidx * 128;
#pragma unroll
                for (int nt = 0; nt < 4; nt++) {
                    int e = warp_n * 32 + nt * 8 + tg * 2;
                    float h0 = (acc[mt][nt][hf * 2 + 0] - mu) * rs * gwsm[e]     + gbsm[e];
                    float h1 = (acc[mt][nt][hf * 2 + 1] - mu) * rs * gwsm[e + 1] + gbsm[e + 1];
                    *(__half2*)&g_hh[rowbase + e] = __floats2half2_rn(h0, h1);
                }
            }
        }
    } else {
        // ======== plain / SiLU epilogue =========================================
#pragma unroll
        for (int mt = 0; mt < 4; mt++) {
#pragma unroll
            for (int nt = 0; nt < 4; nt++) {
                int col  = n0 + warp_n * 32 + nt * 8 + tg * 2;
                int rowa = m0 + warp_m * 64 + mt * 16 + g;
                float2 v0, v1;
                v0.x = acc[mt][nt][0]; v0.y = acc[mt][nt][1];
                v1.x = acc[mt][nt][2]; v1.y = acc[mt][nt][3];
                if (MODE == 1) {
                    float b0 = bias[col], b1 = bias[col + 1];
                    v0.x += b0; v0.y += b1; v1.x += b0; v1.y += b1;
                    v0.x = v0.x / (1.0f + expf(-v0.x));
                    v0.y = v0.y / (1.0f + expf(-v0.y));
                    v1.x = v1.x / (1.0f + expf(-v1.x));
                    v1.y = v1.y / (1.0f + expf(-v1.y));
                    __half* C = (__half*)Cout;
                    *(__half2*)&C[(size_t)rowa * DD + col]       = __floats2half2_rn(v0.x, v0.y);
                    *(__half2*)&C[(size_t)(rowa + 8) * DD + col] = __floats2half2_rn(v1.x, v1.y);
                } else {
                    float* C = (float*)Cout;
                    *(float2*)&C[(size_t)rowa * DD + col]       = v0;
                    *(float2*)&C[(size_t)(rowa + 8) * DD + col] = v1;
                }
            }
        }
    }
}

// ---------------- gates: i,f from xconv(fp16); o from x(fp16); smem weights ----
__device__ __forceinline__ float softcapf(float x) {
    return CAPV * tanhf(x * (1.0f / CAPV));
}

__global__ void __launch_bounds__(256)
gates_kernel(const float* __restrict__ ib, const float* __restrict__ fb,
             const float* __restrict__ ob,
             const float* __restrict__ iw, const float* __restrict__ fw,
             const float* __restrict__ ow) {
    __shared__ __half wsm[24 * 1024];      // 48KB: i0-7, f0-7, o0-7

    const int t = threadIdx.x;
    for (int idx = t; idx < 24 * 1024; idx += 256) {
        int gg = idx >> 10, k = idx & 1023;
        float v = (gg < 8) ? iw[gg * 1024 + k]
                : (gg < 16) ? fw[(gg - 8) * 1024 + k]
                            : ow[(gg - 16) * 1024 + k];
        wsm[idx] = __float2half_rn(v);
    }
    __syncthreads();

    const int wid  = t >> 5;
    const int lane = t & 31;

    for (int row = blockIdx.x * 8 + wid; row < BB; row += gridDim.x * 8) {
        const uint4* xc4 = (const uint4*)(g_xch + (size_t)row * 1024);
        const uint4* xx4 = (const uint4*)(g_xh  + (size_t)row * 1024);
        float xcf[32], xxf[32];
#pragma unroll
        for (int j = 0; j < 4; j++) {
            uint4 vc = xc4[lane + j * 32];
            uint4 vx = xx4[lane + j * 32];
            const __half2* hc = (const __half2*)&vc;
            const __half2* hx = (const __half2*)&vx;
#pragma unroll
            for (int q = 0; q < 4; q++) {
                float2 fc = __half22float2(hc[q]);
                float2 fx = __half22float2(hx[q]);
                xcf[j * 8 + q * 2]     = fc.x; xcf[j * 8 + q * 2 + 1] = fc.y;
                xxf[j * 8 + q * 2]     = fx.x; xxf[j * 8 + q * 2 + 1] = fx.y;
            }
        }
#pragma unroll 1
        for (int gg = 0; gg < 24; gg++) {
            const uint4* w4 = (const uint4*)(wsm + gg * 1024);
            const float* xf = (gg < 16) ? xcf : xxf;
            float acc = 0.0f;
#pragma unroll
            for (int j = 0; j < 4; j++) {
                uint4 wv = w4[lane + j * 32];
                const __half2* hw = (const __half2*)&wv;
#pragma unroll
                for (int q = 0; q < 4; q++) {
                    float2 fw2 = __half22float2(hw[q]);
                    acc += xf[j * 8 + q * 2] * fw2.x + xf[j * 8 + q * 2 + 1] * fw2.y;
                }
            }
#pragma unroll
            for (int off = 16; off > 0; off >>= 1)
                acc += __shfl_xor_sync(0xffffffffu, acc, off);
            if (lane == 0) {
                if (gg < 8)       g_it[row * 8 + gg]        = softcapf(acc + ib[gg]);
                else if (gg < 16) g_ft[row * 8 + gg - 8]    = softcapf(acc + fb[gg - 8]);
                else {
                    float vo = softcapf(acc + ob[gg - 16]);
                    g_og[row * 8 + gg - 16] = 1.0f / (1.0f + expf(-vo));
                }
            }
        }
    }
}

// ---------------- launch --------------------------------------------------------
extern "C" void kernel_launch(void* const* d_in, const int* in_sizes, int n_in,
                              void* d_out, int out_size) {
    const float* x      = (const float*)d_in[0];
    const float* c      = (const float*)d_in[1];
    const float* n      = (const float*)d_in[2];
    const float* m      = (const float*)d_in[3];
    const float* conv_w = (const float*)d_in[4];
    const float* conv_b = (const float*)d_in[5];
    const float* z_w    = (const float*)d_in[6];
    const float* i_w    = (const float*)d_in[7];
    const float* i_b    = (const float*)d_in[8];
    const float* f_w    = (const float*)d_in[9];
    const float* f_b    = (const float*)d_in[10];
    const float* o_w    = (const float*)d_in[11];
    const float* o_b    = (const float*)d_in[12];
    const float* gn_w   = (const float*)d_in[13];
    const float* gn_b   = (const float*)d_in[14];
    const float* out_w  = (const float*)d_in[15];

    float* out   = (float*)d_out;
    float* c_out = out   + (size_t)BB * DD;
    float* n_out = c_out + (size_t)BB * DD;
    float* m_out = n_out + (size_t)BB * DD;

    __half *p_xh, *p_xch, *p_hh, *p_wchi, *p_wzhi, *p_wohi;
    cudaGetSymbolAddress((void**)&p_xh,   g_xh);
    cudaGetSymbolAddress((void**)&p_xch,  g_xch);
    cudaGetSymbolAddress((void**)&p_hh,   g_hh);
    cudaGetSymbolAddress((void**)&p_wchi, g_wc_hi);
    cudaGetSymbolAddress((void**)&p_wzhi, g_wz_hi);
    cudaGetSymbolAddress((void**)&p_wohi, g_wo_hi);

    cudaFuncSetAttribute((const void*)gemm2_kernel<0>, cudaFuncAttributeMaxDynamicSharedMemorySize, GEMM_SMEM);
    cudaFuncSetAttribute((const void*)gemm2_kernel<1>, cudaFuncAttributeMaxDynamicSharedMemorySize, GEMM_SMEM);
    cudaFuncSetAttribute((const void*)gemm2_kernel<2>, cudaFuncAttributeMaxDynamicSharedMemorySize, GEMM_SMEM);

    tohalf_kernel<<<(BB * DD / 8 + 255) / 256, 256>>>(x, p_xh, BB * DD / 8);
    wconv_kernel<<<(DD * DD + 255) / 256, 256>>>(conv_w);
    tohalf_kernel<<<(DD * DD / 8 + 255) / 256, 256>>>(z_w,   p_wzhi, DD * DD / 8);
    tohalf_kernel<<<(DD * DD / 8 + 255) / 256, 256>>>(out_w, p_wohi, DD * DD / 8);

    dim3 gg(DD / 128, BB / 128);   // (8, 256)

    // conv GEMM -> SiLU -> fp16 xconv
    gemm2_kernel<1><<<gg, 256, GEMM_SMEM>>>(
        p_xh, p_wchi, conv_b, p_xch,
        nullptr, nullptr, nullptr, nullptr, nullptr, nullptr, nullptr, nullptr);
    // gate projections
    gates_kernel<<<592, 256>>>(i_b, f_b, o_b, i_w, f_w, o_w);
    // z GEMM + fused gating/LayerNorm epilogue
    gemm2_kernel<2><<<gg, 256, GEMM_SMEM>>>(
        p_xh, p_wzhi, nullptr, nullptr,
        c, n, m, gn_w, gn_b, c_out, n_out, m_out);
    // out projection -> fp32
    gemm2_kernel<0><<<gg, 256, GEMM_SMEM>>>(
        p_hh, p_wohi, nullptr, out,
        nullptr, nullptr, nullptr, nullptr, nullptr, nullptr, nullptr, nullptr);
}

// round 12
// speedup vs baseline: 1.0172x; 1.0172x over previous
#include <cuda_runtime.h>
#include <cuda_fp16.h>
#include <math.h>
#include <stdint.h>

#define BB   32768
#define DD   1024
#define NHEAD 8
#define KTAP 4
#define EPSV 1e-6f
#define CAPV 15.0f

// ---------------- scratch (allocation-free, __device__ globals) ----------------
__device__ __half g_xh[(size_t)BB * DD];     // x as fp16
__device__ __half g_xch[(size_t)BB * DD];    // SiLU(conv tap) as fp16
__device__ __half g_hh[(size_t)BB * DD];     // h_norm as fp16
__device__ __half g_wc_hi[DD * DD];          // conv last tap
__device__ __half g_wz_hi[DD * DD];          // z_w
__device__ __half g_wo_hi[DD * DD];          // out_w
__device__ float g_it[BB * NHEAD];
__device__ float g_ft[BB * NHEAD];
__device__ float g_og[BB * NHEAD];

// ================= low-level helpers (arch-portable, sm_80+) ===================
__device__ __forceinline__ uint32_t smem_u32(const void* p) {
    uint32_t a;
    asm("{ .reg .u64 t; cvta.to.shared.u64 t, %1; cvt.u32.u64 %0, t; }" : "=r"(a) : "l"(p));
    return a;
}
__device__ __forceinline__ void cp16(uint32_t dst, const void* src) {
    asm volatile("cp.async.cg.shared.global [%0], [%1], 16;" :: "r"(dst), "l"(src));
}
__device__ __forceinline__ void cp_commit() {
    asm volatile("cp.async.commit_group;" ::: "memory");
}
__device__ __forceinline__ void cp_wait0() {
    asm volatile("cp.async.wait_group 0;" ::: "memory");
}
__device__ __forceinline__ void cp_wait1() {
    asm volatile("cp.async.wait_group 1;" ::: "memory");
}
__device__ __forceinline__ void ldsm4(uint32_t* r, uint32_t addr) {
    asm volatile("ldmatrix.sync.aligned.m8n8.x4.shared.b16 {%0,%1,%2,%3}, [%4];"
                 : "=r"(r[0]), "=r"(r[1]), "=r"(r[2]), "=r"(r[3]) : "r"(addr));
}
__device__ __forceinline__ void mma_f16(float* d, const uint32_t* a, const uint32_t* b) {
    asm volatile(
        "mma.sync.aligned.m16n8k16.row.col.f32.f16.f16.f32 "
        "{%0,%1,%2,%3}, {%4,%5,%6,%7}, {%8,%9}, {%0,%1,%2,%3};"
        : "+f"(d[0]), "+f"(d[1]), "+f"(d[2]), "+f"(d[3])
        : "r"(a[0]), "r"(a[1]), "r"(a[2]), "r"(a[3]), "r"(b[0]), "r"(b[1]));
}

// ================= conversion kernels ==========================================
__global__ void tohalf_kernel(const float* __restrict__ in, __half* __restrict__ out, int n8) {
    int i = blockIdx.x * blockDim.x + threadIdx.x;
    if (i >= n8) return;
    float4 a = ((const float4*)in)[i * 2];
    float4 b = ((const float4*)in)[i * 2 + 1];
    __half2 h[4];
    h[0] = __floats2half2_rn(a.x, a.y);
    h[1] = __floats2half2_rn(a.z, a.w);
    h[2] = __floats2half2_rn(b.x, b.y);
    h[3] = __floats2half2_rn(b.z, b.w);
    ((uint4*)out)[i] = *(uint4*)h;
}

__global__ void wconv_kernel(const float* __restrict__ conv_w) {
    int i = blockIdx.x * blockDim.x + threadIdx.x;
    if (i >= DD * DD) return;
    g_wc_hi[i] = __float2half_rn(conv_w[(size_t)i * KTAP + (KTAP - 1)]);
}

// ================= tensor-core GEMM =============================================
// C[M,1024] = A[M,1024] * W[1024,1024]^T, fp16 operands, fp32 accum.
// Block 128x128, BK=64, 3 stages (cp.async depth-2), one barrier per k-iter,
// 2 CTAs/SM. 8 warps as 2(M) x 4(N), warp tile 64x32.
// MODE 0: fp32 out. MODE 1: SiLU(y+bias) -> fp16 out.
// MODE 2: fused sLSTM gating + per-head LayerNorm epilogue (tile = one head).
#define TSTRIDE   144                     // 128B data + 16B pad (conflict-free)
#define TENSOR_B  (128 * TSTRIDE)         // 18432
#define STAGE_B   (2 * TENSOR_B)          // Ah, Whi = 36864
#define NSTAGE    3
#define GEMM_SMEM (NSTAGE * STAGE_B)      // 110592

template <int MODE>
__global__ void __launch_bounds__(256, 2)
gemm2_kernel(const __half* __restrict__ Ah, const __half* __restrict__ Whi,
             const float* __restrict__ bias, void* __restrict__ Cout,
             const float* __restrict__ cc, const float* __restrict__ nn_,
             const float* __restrict__ mm_,
             const float* __restrict__ gw, const float* __restrict__ gb,
             float* __restrict__ c_out, float* __restrict__ n_out,
             float* __restrict__ m_out) {
    extern __shared__ char dynsmem[];
    const uint32_t sbase = smem_u32(dynsmem);

    const int t      = threadIdx.x;
    const int lane   = t & 31;
    const int wid    = t >> 5;
    const int warp_m = wid >> 2;
    const int warp_n = wid & 3;
    const int m0     = blockIdx.y * 128;
    const int n0     = blockIdx.x * 128;

    const char* srcs[2];
    srcs[0] = (const char*)(Ah  + (size_t)m0 * DD);
    srcs[1] = (const char*)(Whi + (size_t)n0 * DD);

    // 2048 16B chunks per stage (2 tensors x 128 rows x 8 chunks), 8 per thread
    int l_tensor[8], l_row[8], l_ch[8];
#pragma unroll
    for (int j = 0; j < 8; j++) {
        int cid = t + j * 256;
        l_tensor[j] = cid >> 10;
        int rc = cid & 1023;
        l_row[j] = rc >> 3;
        l_ch[j]  = rc & 7;
    }

    auto load_stage = [&](int stg, int kiter) {
        uint32_t sdst = sbase + stg * STAGE_B;
        int k0b = kiter * 128;                // 64 fp16 = 128B along K
#pragma unroll
        for (int j = 0; j < 8; j++) {
            uint32_t dst = sdst + l_tensor[j] * TENSOR_B + l_row[j] * TSTRIDE + l_ch[j] * 16;
            const char* src = srcs[l_tensor[j]] + (size_t)l_row[j] * 2048 + k0b + l_ch[j] * 16;
            cp16(dst, src);
        }
    };

    float acc[4][4][4];
#pragma unroll
    for (int i = 0; i < 4; i++)
#pragma unroll
        for (int j = 0; j < 4; j++)
#pragma unroll
            for (int q = 0; q < 4; q++) acc[i][j][q] = 0.0f;

    const uint32_t offA = (uint32_t)((warp_m * 64 + (lane & 15)) * TSTRIDE + (lane >> 4) * 16);
    const uint32_t offB = (uint32_t)((warp_n * 32 + ((lane >> 4) << 3) + (lane & 7)) * TSTRIDE
                        + (((lane >> 3) & 1) << 4));

    load_stage(0, 0); cp_commit();
    load_stage(1, 1); cp_commit();

    for (int i = 0; i < 16; i++) {
        if (i + 1 < 16) cp_wait1();   // group(i) done; group(i+1) may fly
        else            cp_wait0();   // last: only group(15) pending
        __syncthreads();              // stage (i+2)%3 consumers (iter i-1) done
        if (i + 2 < 16) {
            load_stage((i + 2) % NSTAGE, i + 2);
            cp_commit();
        }
        const uint32_t stg = sbase + (i % NSTAGE) * STAGE_B;
#pragma unroll
        for (int k16 = 0; k16 < 4; k16++) {
            const uint32_t koff = k16 * 32;
            uint32_t bh[2][4];
#pragma unroll
            for (int p = 0; p < 2; p++)
                ldsm4(bh[p], stg + TENSOR_B + offB + p * (16 * TSTRIDE) + koff);
#pragma unroll
            for (int mt = 0; mt < 4; mt++) {
                uint32_t ah[4];
                ldsm4(ah, stg + offA + mt * (16 * TSTRIDE) + koff);
#pragma unroll
                for (int nt = 0; nt < 4; nt++)
                    mma_f16(acc[mt][nt], ah, &bh[nt >> 1][(nt & 1) * 2]);
            }
        }
    }

    const int g  = lane >> 2;
    const int tg = lane & 3;

    if (MODE == 2) {
        // ======== fused gating + per-head LayerNorm epilogue ====================
        const int hidx = blockIdx.x;   // tile n-range == head hidx
        float* ep    = (float*)dynsmem;
        float* sig   = ep;            // [128] i gate (exp)
        float* sfg   = ep + 128;      // [128] f gate (exp)
        float* sog   = ep + 256;      // [128] o gate (sigmoid)
        float* gwsm  = ep + 384;      // [128]
        float* gbsm  = ep + 512;      // [128]
        float* rsum  = ep + 640;      // [4][128]
        float* rsq   = ep + 1152;     // [4][128]

        __syncthreads();              // mainloop smem dead
        if (t < 128) {
            int bh_i = (m0 + t) * 8 + hidx;
            float it  = g_it[bh_i];
            float ft  = g_ft[bh_i];
            float m0v = mm_[bh_i];
            float fl  = -log1pf(expf(-ft));
            float mn  = fmaxf(fl + m0v, it);
            sig[t] = expf(it - mn);
            sfg[t] = expf(fl + m0v - mn);
            sog[t] = g_og[bh_i];
            m_out[bh_i] = mn;
        } else {
            int e = t - 128;
            gwsm[e] = gw[hidx * 128 + e];
            gbsm[e] = gb[hidx * 128 + e];
        }
        __syncthreads();

        // phase 1: c_new/n_new, h, partial row sums
#pragma unroll
        for (int mt = 0; mt < 4; mt++) {
#pragma unroll
            for (int hf = 0; hf < 2; hf++) {
                int r = warp_m * 64 + mt * 16 + g + hf * 8;
                float igv = sig[r], fgv = sfg[r], ogv = sog[r];
                size_t rowbase = (size_t)(m0 + r) * 1024 + hidx * 128;
                float s = 0.f, sq = 0.f;
#pragma unroll
                for (int nt = 0; nt < 4; nt++) {
                    int e = warp_n * 32 + nt * 8 + tg * 2;
                    float2 cv = *(const float2*)&cc[rowbase + e];
                    float2 nv = *(const float2*)&nn_[rowbase + e];
                    float z0 = acc[mt][nt][hf * 2 + 0];
                    float z1 = acc[mt][nt][hf * 2 + 1];
                    float cn0 = fgv * cv.x + igv * z0;
                    float cn1 = fgv * cv.y + igv * z1;
                    float nn0 = fgv * nv.x + igv;
                    float nn1 = fgv * nv.y + igv;
                    *(float2*)&c_out[rowbase + e] = make_float2(cn0, cn1);
                    *(float2*)&n_out[rowbase + e] = make_float2(nn0, nn1);
                    float h0 = ogv * cn0 / (nn0 + EPSV);
                    float h1 = ogv * cn1 / (nn1 + EPSV);
                    acc[mt][nt][hf * 2 + 0] = h0;
                    acc[mt][nt][hf * 2 + 1] = h1;
                    s += h0 + h1;
                    sq += h0 * h0 + h1 * h1;
                }
                s  += __shfl_xor_sync(0xffffffffu, s, 1);
                s  += __shfl_xor_sync(0xffffffffu, s, 2);
                sq += __shfl_xor_sync(0xffffffffu, sq, 1);
                sq += __shfl_xor_sync(0xffffffffu, sq, 2);
                if (tg == 0) {
                    rsum[warp_n * 128 + r] = s;
                    rsq[warp_n * 128 + r]  = sq;
                }
            }
        }
        __syncthreads();

        // phase 2: normalize + affine -> fp16 h
#pragma unroll
        for (int mt = 0; mt < 4; mt++) {
#pragma unroll
            for (int hf = 0; hf < 2; hf++) {
                int r = warp_m * 64 + mt * 16 + g + hf * 8;
                float s  = rsum[r] + rsum[128 + r] + rsum[256 + r] + rsum[384 + r];
                float sq = rsq[r]  + rsq[128 + r]  + rsq[256 + r]  + rsq[384 + r];
                float mu  = s * (1.0f / 128.0f);
                float var = sq * (1.0f / 128.0f) - mu * mu;
                float rs  = rsqrtf(var + EPSV);
                size_t rowbase = (size_t)(m0 + r) * 1024 + hidx * 128;
#pragma unroll
                for (int nt = 0; nt < 4; nt++) {
                    int e = warp_n * 32 + nt * 8 + tg * 2;
                    float h0 = (acc[mt][nt][hf * 2 + 0] - mu) * rs * gwsm[e]     + gbsm[e];
                    float h1 = (acc[mt][nt][hf * 2 + 1] - mu) * rs * gwsm[e + 1] + gbsm[e + 1];
                    *(__half2*)&g_hh[rowbase + e] = __floats2half2_rn(h0, h1);
                }
            }
        }
    } else {
        // ======== plain / SiLU epilogue =========================================
#pragma unroll
        for (int mt = 0; mt < 4; mt++) {
#pragma unroll
            for (int nt = 0; nt < 4; nt++) {
                int col  = n0 + warp_n * 32 + nt * 8 + tg * 2;
                int rowa = m0 + warp_m * 64 + mt * 16 + g;
                float2 v0, v1;
                v0.x = acc[mt][nt][0]; v0.y = acc[mt][nt][1];
                v1.x = acc[mt][nt][2]; v1.y = acc[mt][nt][3];
                if (MODE == 1) {
                    float b0 = bias[col], b1 = bias[col + 1];
                    v0.x += b0; v0.y += b1; v1.x += b0; v1.y += b1;
                    v0.x = v0.x / (1.0f + expf(-v0.x));
                    v0.y = v0.y / (1.0f + expf(-v0.y));
                    v1.x = v1.x / (1.0f + expf(-v1.x));
                    v1.y = v1.y / (1.0f + expf(-v1.y));
                    __half* C = (__half*)Cout;
                    *(__half2*)&C[(size_t)rowa * DD + col]       = __floats2half2_rn(v0.x, v0.y);
                    *(__half2*)&C[(size_t)(rowa + 8) * DD + col] = __floats2half2_rn(v1.x, v1.y);
                } else {
                    float* C = (float*)Cout;
                    *(float2*)&C[(size_t)rowa * DD + col]       = v0;
                    *(float2*)&C[(size_t)(rowa + 8) * DD + col] = v1;
                }
            }
        }
    }
}

// ---------------- gates: i,f from xconv(fp16); o from x(fp16); smem weights ----
__device__ __forceinline__ float softcapf(float x) {
    return CAPV * tanhf(x * (1.0f / CAPV));
}

__global__ void __launch_bounds__(256)
gates_kernel(const float* __restrict__ ib, const float* __restrict__ fb,
             const float* __restrict__ ob,
             const float* __restrict__ iw, const float* __restrict__ fw,
             const float* __restrict__ ow) {
    __shared__ __half wsm[24 * 1024];      // 48KB: i0-7, f0-7, o0-7

    const int t = threadIdx.x;
    for (int idx = t; idx < 24 * 1024; idx += 256) {
        int gg = idx >> 10, k = idx & 1023;
        float v = (gg < 8) ? iw[gg * 1024 + k]
                : (gg < 16) ? fw[(gg - 8) * 1024 + k]
                            : ow[(gg - 16) * 1024 + k];
        wsm[idx] = __float2half_rn(v);
    }
    __syncthreads();

    const int wid  = t >> 5;
    const int lane = t & 31;

    for (int row = blockIdx.x * 8 + wid; row < BB; row += gridDim.x * 8) {
        const uint4* xc4 = (const uint4*)(g_xch + (size_t)row * 1024);
        const uint4* xx4 = (const uint4*)(g_xh  + (size_t)row * 1024);
        float xcf[32], xxf[32];
#pragma unroll
        for (int j = 0; j < 4; j++) {
            uint4 vc = xc4[lane + j * 32];
            uint4 vx = xx4[lane + j * 32];
            const __half2* hc = (const __half2*)&vc;
            const __half2* hx = (const __half2*)&vx;
#pragma unroll
            for (int q = 0; q < 4; q++) {
                float2 fc = __half22float2(hc[q]);
                float2 fx = __half22float2(hx[q]);
                xcf[j * 8 + q * 2]     = fc.x; xcf[j * 8 + q * 2 + 1] = fc.y;
                xxf[j * 8 + q * 2]     = fx.x; xxf[j * 8 + q * 2 + 1] = fx.y;
            }
        }
#pragma unroll 1
        for (int gg = 0; gg < 24; gg++) {
            const uint4* w4 = (const uint4*)(wsm + gg * 1024);
            const float* xf = (gg < 16) ? xcf : xxf;
            float acc = 0.0f;
#pragma unroll
            for (int j = 0; j < 4; j++) {
                uint4 wv = w4[lane + j * 32];
                const __half2* hw = (const __half2*)&wv;
#pragma unroll
                for (int q = 0; q < 4; q++) {
                    float2 fw2 = __half22float2(hw[q]);
                    acc += xf[j * 8 + q * 2] * fw2.x + xf[j * 8 + q * 2 + 1] * fw2.y;
                }
            }
#pragma unroll
            for (int off = 16; off > 0; off >>= 1)
                acc += __shfl_xor_sync(0xffffffffu, acc, off);
            if (lane == 0) {
                if (gg < 8)       g_it[row * 8 + gg]        = softcapf(acc + ib[gg]);
                else if (gg < 16) g_ft[row * 8 + gg - 8]    = softcapf(acc + fb[gg - 8]);
                else {
                    float vo = softcapf(acc + ob[gg - 16]);
                    g_og[row * 8 + gg - 16] = 1.0f / (1.0f + expf(-vo));
                }
            }
        }
    }
}

// ---------------- launch --------------------------------------------------------
extern "C" void kernel_launch(void* const* d_in, const int* in_sizes, int n_in,
                              void* d_out, int out_size) {
    const float* x      = (const float*)d_in[0];
    const float* c      = (const float*)d_in[1];
    const float* n      = (const float*)d_in[2];
    const float* m      = (const float*)d_in[3];
    const float* conv_w = (const float*)d_in[4];
    const float* conv_b = (const float*)d_in[5];
    const float* z_w    = (const float*)d_in[6];
    const float* i_w    = (const float*)d_in[7];
    const float* i_b    = (const float*)d_in[8];
    const float* f_w    = (const float*)d_in[9];
    const float* f_b    = (const float*)d_in[10];
    const float* o_w    = (const float*)d_in[11];
    const float* o_b    = (const float*)d_in[12];
    const float* gn_w   = (const float*)d_in[13];
    const float* gn_b   = (const float*)d_in[14];
    const float* out_w  = (const float*)d_in[15];

    float* out   = (float*)d_out;
    float* c_out = out   + (size_t)BB * DD;
    float* n_out = c_out + (size_t)BB * DD;
    float* m_out = n_out + (size_t)BB * DD;

    __half *p_xh, *p_xch, *p_hh, *p_wchi, *p_wzhi, *p_wohi;
    cudaGetSymbolAddress((void**)&p_xh,   g_xh);
    cudaGetSymbolAddress((void**)&p_xch,  g_xch);
    cudaGetSymbolAddress((void**)&p_hh,   g_hh);
    cudaGetSymbolAddress((void**)&p_wchi, g_wc_hi);
    cudaGetSymbolAddress((void**)&p_wzhi, g_wz_hi);
    cudaGetSymbolAddress((void**)&p_wohi, g_wo_hi);

    cudaFuncSetAttribute((const void*)gemm2_kernel<0>, cudaFuncAttributeMaxDynamicSharedMemorySize, GEMM_SMEM);
    cudaFuncSetAttribute((const void*)gemm2_kernel<1>, cudaFuncAttributeMaxDynamicSharedMemorySize, GEMM_SMEM);
    cudaFuncSetAttribute((const void*)gemm2_kernel<2>, cudaFuncAttributeMaxDynamicSharedMemorySize, GEMM_SMEM);

    tohalf_kernel<<<(BB * DD / 8 + 255) / 256, 256>>>(x, p_xh, BB * DD / 8);
    wconv_kernel<<<(DD * DD + 255) / 256, 256>>>(conv_w);
    tohalf_kernel<<<(DD * DD / 8 + 255) / 256, 256>>>(z_w,   p_wzhi, DD * DD / 8);
    tohalf_kernel<<<(DD * DD / 8 + 255) / 256, 256>>>(out_w, p_wohi, DD * DD / 8);

    dim3 gg(DD / 128, BB / 128);   // (8, 256)

    // conv GEMM -> SiLU -> fp16 xconv
    gemm2_kernel<1><<<gg, 256, GEMM_SMEM>>>(
        p_xh, p_wchi, conv_b, p_xch,
        nullptr, nullptr, nullptr, nullptr, nullptr, nullptr, nullptr, nullptr);
    // gate projections
    gates_kernel<<<592, 256>>>(i_b, f_b, o_b, i_w, f_w, o_w);
    // z GEMM + fused gating/LayerNorm epilogue
    gemm2_kernel<2><<<gg, 256, GEMM_SMEM>>>(
        p_xh, p_wzhi, nullptr, nullptr,
        c, n, m, gn_w, gn_b, c_out, n_out, m_out);
    // out projection -> fp32
    gemm2_kernel<0><<<gg, 256, GEMM_SMEM>>>(
        p_hh, p_wohi, nullptr, out,
        nullptr, nullptr, nullptr, nullptr, nullptr, nullptr, nullptr, nullptr);
}

// round 13
// speedup vs baseline: 1.4731x; 1.4482x over previous
#include <cuda_runtime.h>
#include <cuda_fp16.h>
#include <math.h>
#include <stdint.h>

#define BB   32768
#define DD   1024
#define NHEAD 8
#define KTAP 4
#define EPSV 1e-6f
#define CAPV 15.0f

// ---------------- scratch (allocation-free, __device__ globals) ----------------
__device__ __half g_xh[(size_t)BB * DD];     // x as fp16
__device__ __half g_xch[(size_t)BB * DD];    // SiLU(conv tap) as fp16
__device__ __half g_hh[(size_t)BB * DD];     // h_norm as fp16
__device__ __half g_wc_hi[DD * DD];          // conv last tap
__device__ __half g_wz_hi[DD * DD];          // z_w
__device__ __half g_wo_hi[DD * DD];          // out_w
__device__ float g_it[BB * NHEAD];
__device__ float g_ft[BB * NHEAD];
__device__ float g_og[BB * NHEAD];

// ================= low-level helpers (arch-portable, sm_80+) ===================
__device__ __forceinline__ uint32_t smem_u32(const void* p) {
    uint32_t a;
    asm("{ .reg .u64 t; cvta.to.shared.u64 t, %1; cvt.u32.u64 %0, t; }" : "=r"(a) : "l"(p));
    return a;
}
__device__ __forceinline__ void cp16(uint32_t dst, const void* src) {
    asm volatile("cp.async.cg.shared.global [%0], [%1], 16;" :: "r"(dst), "l"(src));
}
__device__ __forceinline__ void cp_commit() {
    asm volatile("cp.async.commit_group;" ::: "memory");
}
__device__ __forceinline__ void cp_wait0() {
    asm volatile("cp.async.wait_group 0;" ::: "memory");
}
__device__ __forceinline__ void ldsm4(uint32_t* r, uint32_t addr) {
    asm volatile("ldmatrix.sync.aligned.m8n8.x4.shared.b16 {%0,%1,%2,%3}, [%4];"
                 : "=r"(r[0]), "=r"(r[1]), "=r"(r[2]), "=r"(r[3]) : "r"(addr));
}
__device__ __forceinline__ void mma_f16(float* d, const uint32_t* a, const uint32_t* b) {
    asm volatile(
        "mma.sync.aligned.m16n8k16.row.col.f32.f16.f16.f32 "
        "{%0,%1,%2,%3}, {%4,%5,%6,%7}, {%8,%9}, {%0,%1,%2,%3};"
        : "+f"(d[0]), "+f"(d[1]), "+f"(d[2]), "+f"(d[3])
        : "r"(a[0]), "r"(a[1]), "r"(a[2]), "r"(a[3]), "r"(b[0]), "r"(b[1]));
}

// ================= conversion kernels ==========================================
__global__ void tohalf_kernel(const float* __restrict__ in, __half* __restrict__ out, int n8) {
    int i = blockIdx.x * blockDim.x + threadIdx.x;
    if (i >= n8) return;
    float4 a = ((const float4*)in)[i * 2];
    float4 b = ((const float4*)in)[i * 2 + 1];
    __half2 h[4];
    h[0] = __floats2half2_rn(a.x, a.y);
    h[1] = __floats2half2_rn(a.z, a.w);
    h[2] = __floats2half2_rn(b.x, b.y);
    h[3] = __floats2half2_rn(b.z, b.w);
    ((uint4*)out)[i] = *(uint4*)h;
}

__global__ void wconv_kernel(const float* __restrict__ conv_w) {
    int i = blockIdx.x * blockDim.x + threadIdx.x;
    if (i >= DD * DD) return;
    g_wc_hi[i] = __float2half_rn(conv_w[(size_t)i * KTAP + (KTAP - 1)]);
}

// ================= tensor-core GEMM =============================================
// C[M,1024] = A[M,1024] * W[1024,1024]^T, fp16 operands, fp32 accum.
// NTERMS=2 adds (Ah*2^-10)*(Wlo*2^10) error compensation (unused this round).
// MODE 0: fp32 out. MODE 1: SiLU(y+bias) -> fp16 out.
// MODE 2: fused sLSTM gating + per-head LayerNorm epilogue (tile = one head).
// Layout/occupancy pinned identical to the round-10 artifact.
#define TSTRIDE   144                     // 128B data + 16B pad (conflict-free)
#define TENSOR_B  (128 * TSTRIDE)         // 18432
#define STAGE_B   (3 * TENSOR_B)          // slots: Ah, Whi, (Wlo)
#define NSTAGE    2
#define GEMM_SMEM (NSTAGE * STAGE_B)      // 110592 -> exactly 2 CTAs/SM

template <int MODE, int NTERMS>
__global__ void __launch_bounds__(256, 2)
gemm2_kernel(const __half* __restrict__ Ah, const __half* __restrict__ Whi,
             const __half* __restrict__ Wlo, const float* __restrict__ bias,
             void* __restrict__ Cout,
             const float* __restrict__ cc, const float* __restrict__ nn_,
             const float* __restrict__ mm_,
             const float* __restrict__ gw, const float* __restrict__ gb,
             float* __restrict__ c_out, float* __restrict__ n_out,
             float* __restrict__ m_out) {
    extern __shared__ char dynsmem[];
    const uint32_t sbase = smem_u32(dynsmem);

    const int t      = threadIdx.x;
    const int lane   = t & 31;
    const int wid    = t >> 5;
    const int warp_m = wid >> 2;
    const int warp_n = wid & 3;
    const int m0     = blockIdx.y * 128;
    const int n0     = blockIdx.x * 128;

    const char* srcs[3];
    srcs[0] = (const char*)(Ah  + (size_t)m0 * DD);
    srcs[1] = (const char*)(Whi + (size_t)n0 * DD);
    srcs[2] = (const char*)(NTERMS == 2 ? (Wlo + (size_t)n0 * DD) : (const __half*)0);

    constexpr int NCHUNK = (NTERMS == 2) ? 12 : 8;   // 16B chunks per thread/stage
    int l_tensor[NCHUNK], l_row[NCHUNK], l_ch[NCHUNK];
#pragma unroll
    for (int j = 0; j < NCHUNK; j++) {
        int cid = t + j * 256;
        l_tensor[j] = cid >> 10;
        int rc = cid & 1023;
        l_row[j] = rc >> 3;
        l_ch[j]  = rc & 7;
    }

    auto load_stage = [&](int stg, int kiter) {
        uint32_t sdst = sbase + stg * STAGE_B;
        int k0b = kiter * 128;                // 64 fp16 = 128B along K
#pragma unroll
        for (int j = 0; j < NCHUNK; j++) {
            uint32_t dst = sdst + l_tensor[j] * TENSOR_B + l_row[j] * TSTRIDE + l_ch[j] * 16;
            const char* src = srcs[l_tensor[j]] + (size_t)l_row[j] * 2048 + k0b + l_ch[j] * 16;
            cp16(dst, src);
        }
    };

    float acc[4][4][4];
#pragma unroll
    for (int i = 0; i < 4; i++)
#pragma unroll
        for (int j = 0; j < 4; j++)
#pragma unroll
            for (int q = 0; q < 4; q++) acc[i][j][q] = 0.0f;

    const uint32_t offA = (uint32_t)((warp_m * 64 + (lane & 15)) * TSTRIDE + (lane >> 4) * 16);
    const uint32_t offB = (uint32_t)((warp_n * 32 + ((lane >> 4) << 3) + (lane & 7)) * TSTRIDE
                        + (((lane >> 3) & 1) << 4));
    const __half2 dscale = __float2half2_rn(0.0009765625f);   // 2^-10 exact

    load_stage(0, 0);
    cp_commit();

    for (int i = 0; i < 16; i++) {
        cp_wait0();
        __syncthreads();
        if (i + 1 < 16) {
            load_stage((i + 1) & 1, i + 1);
            cp_commit();
        }
        const uint32_t stg = sbase + (i & 1) * STAGE_B;
#pragma unroll
        for (int k16 = 0; k16 < 4; k16++) {
            const uint32_t koff = k16 * 32;
            uint32_t bh[2][4], bl[2][4];
#pragma unroll
            for (int p = 0; p < 2; p++) {
                ldsm4(bh[p], stg + TENSOR_B + offB + p * (16 * TSTRIDE) + koff);
                if (NTERMS == 2)
                    ldsm4(bl[p], stg + 2 * TENSOR_B + offB + p * (16 * TSTRIDE) + koff);
            }
#pragma unroll
            for (int mt = 0; mt < 4; mt++) {
                uint32_t ah[4], as[4];
                ldsm4(ah, stg + offA + mt * (16 * TSTRIDE) + koff);
                if (NTERMS == 2) {
#pragma unroll
                    for (int q = 0; q < 4; q++) {
                        __half2 hv = __hmul2(*(__half2*)&ah[q], dscale);
                        as[q] = *(uint32_t*)&hv;
                    }
                }
#pragma unroll
                for (int nt = 0; nt < 4; nt++) {
                    const uint32_t* bhp = &bh[nt >> 1][(nt & 1) * 2];
                    mma_f16(acc[mt][nt], ah, bhp);
                    if (NTERMS == 2) {
                        const uint32_t* blp = &bl[nt >> 1][(nt & 1) * 2];
                        mma_f16(acc[mt][nt], as, blp);
                    }
                }
            }
        }
    }

    const int g  = lane >> 2;
    const int tg = lane & 3;

    if (MODE == 2) {
        // ======== fused gating + per-head LayerNorm epilogue ====================
        const int hidx = blockIdx.x;   // tile n-range == head hidx
        float* ep    = (float*)dynsmem;
        float* sig   = ep;            // [128] i gate (exp)
        float* sfg   = ep + 128;      // [128] f gate (exp)
        float* sog   = ep + 256;      // [128] o gate (sigmoid)
        float* gwsm  = ep + 384;      // [128]
        float* gbsm  = ep + 512;      // [128]
        float* rsum  = ep + 640;      // [4][128]
        float* rsq   = ep + 1152;     // [4][128]

        __syncthreads();              // mainloop smem dead
        if (t < 128) {
            int bh_i = (m0 + t) * 8 + hidx;
            float it  = g_it[bh_i];
            float ft  = g_ft[bh_i];
            float m0v = mm_[bh_i];
            float fl  = -log1pf(expf(-ft));
            float mn  = fmaxf(fl + m0v, it);
            sig[t] = expf(it - mn);
            sfg[t] = expf(fl + m0v - mn);
            sog[t] = g_og[bh_i];
            m_out[bh_i] = mn;
        } else {
            int e = t - 128;
            gwsm[e] = gw[hidx * 128 + e];
            gbsm[e] = gb[hidx * 128 + e];
        }
        __syncthreads();

        // phase 1: c_new/n_new, h, partial row sums
#pragma unroll
        for (int mt = 0; mt < 4; mt++) {
#pragma unroll
            for (int hf = 0; hf < 2; hf++) {
                int r = warp_m * 64 + mt * 16 + g + hf * 8;
                float igv = sig[r], fgv = sfg[r], ogv = sog[r];
                size_t rowbase = (size_t)(m0 + r) * 1024 + hidx * 128;
                float s = 0.f, sq = 0.f;
#pragma unroll
                for (int nt = 0; nt < 4; nt++) {
                    int e = warp_n * 32 + nt * 8 + tg * 2;
                    float2 cv = *(const float2*)&cc[rowbase + e];
                    float2 nv = *(const float2*)&nn_[rowbase + e];
                    float z0 = acc[mt][nt][hf * 2 + 0];
                    float z1 = acc[mt][nt][hf * 2 + 1];
                    float cn0 = fgv * cv.x + igv * z0;
                    float cn1 = fgv * cv.y + igv * z1;
                    float nn0 = fgv * nv.x + igv;
                    float nn1 = fgv * nv.y + igv;
                    *(float2*)&c_out[rowbase + e] = make_float2(cn0, cn1);
                    *(float2*)&n_out[rowbase + e] = make_float2(nn0, nn1);
                    float h0 = ogv * cn0 / (nn0 + EPSV);
                    float h1 = ogv * cn1 / (nn1 + EPSV);
                    acc[mt][nt][hf * 2 + 0] = h0;
                    acc[mt][nt][hf * 2 + 1] = h1;
                    s += h0 + h1;
                    sq += h0 * h0 + h1 * h1;
                }
                s  += __shfl_xor_sync(0xffffffffu, s, 1);
                s  += __shfl_xor_sync(0xffffffffu, s, 2);
                sq += __shfl_xor_sync(0xffffffffu, sq, 1);
                sq += __shfl_xor_sync(0xffffffffu, sq, 2);
                if (tg == 0) {
                    rsum[warp_n * 128 + r] = s;
                    rsq[warp_n * 128 + r]  = sq;
                }
            }
        }
        __syncthreads();

        // phase 2: normalize + affine -> fp16 h
#pragma unroll
        for (int mt = 0; mt < 4; mt++) {
#pragma unroll
            for (int hf = 0; hf < 2; hf++) {
                int r = warp_m * 64 + mt * 16 + g + hf * 8;
                float s  = rsum[r] + rsum[128 + r] + rsum[256 + r] + rsum[384 + r];
                float sq = rsq[r]  + rsq[128 + r]  + rsq[256 + r]  + rsq[384 + r];
                float mu  = s * (1.0f / 128.0f);
                float var = sq * (1.0f / 128.0f) - mu * mu;
                float rs  = rsqrtf(var + EPSV);
                size_t rowbase = (size_t)(m0 + r) * 1024 + hidx * 128;
#pragma unroll
                for (int nt = 0; nt < 4; nt++) {
                    int e = warp_n * 32 + nt * 8 + tg * 2;
                    float h0 = (acc[mt][nt][hf * 2 + 0] - mu) * rs * gwsm[e]     + gbsm[e];
                    float h1 = (acc[mt][nt][hf * 2 + 1] - mu) * rs * gwsm[e + 1] + gbsm[e + 1];
                    *(__half2*)&g_hh[rowbase + e] = __floats2half2_rn(h0, h1);
                }
            }
        }
    } else {
        // ======== plain / SiLU epilogue =========================================
#pragma unroll
        for (int mt = 0; mt < 4; mt++) {
#pragma unroll
            for (int nt = 0; nt < 4; nt++) {
                int col  = n0 + warp_n * 32 + nt * 8 + tg * 2;
                int rowa = m0 + warp_m * 64 + mt * 16 + g;
                float2 v0, v1;
                v0.x = acc[mt][nt][0]; v0.y = acc[mt][nt][1];
                v1.x = acc[mt][nt][2]; v1.y = acc[mt][nt][3];
                if (MODE == 1) {
                    float b0 = bias[col], b1 = bias[col + 1];
                    v0.x += b0; v0.y += b1; v1.x += b0; v1.y += b1;
                    v0.x = v0.x / (1.0f + expf(-v0.x));
                    v0.y = v0.y / (1.0f + expf(-v0.y));
                    v1.x = v1.x / (1.0f + expf(-v1.x));
                    v1.y = v1.y / (1.0f + expf(-v1.y));
                    __half* C = (__half*)Cout;
                    *(__half2*)&C[(size_t)rowa * DD + col]       = __floats2half2_rn(v0.x, v0.y);
                    *(__half2*)&C[(size_t)(rowa + 8) * DD + col] = __floats2half2_rn(v1.x, v1.y);
                } else {
                    float* C = (float*)Cout;
                    *(float2*)&C[(size_t)rowa * DD + col]       = v0;
                    *(float2*)&C[(size_t)(rowa + 8) * DD + col] = v1;
                }
            }
        }
    }
}

// ---------------- gates: i,f from xconv(fp16); o from x(fp16); smem weights ----
__device__ __forceinline__ float softcapf(float x) {
    return CAPV * tanhf(x * (1.0f / CAPV));
}

__global__ void __launch_bounds__(256)
gates_kernel(const float* __restrict__ ib, const float* __restrict__ fb,
             const float* __restrict__ ob,
             const float* __restrict__ iw, const float* __restrict__ fw,
             const float* __restrict__ ow) {
    __shared__ __half wsm[24 * 1024];      // 48KB: i0-7, f0-7, o0-7

    const int t = threadIdx.x;
    for (int idx = t; idx < 24 * 1024; idx += 256) {
        int gg = idx >> 10, k = idx & 1023;
        float v = (gg < 8) ? iw[gg * 1024 + k]
                : (gg < 16) ? fw[(gg - 8) * 1024 + k]
                            : ow[(gg - 16) * 1024 + k];
        wsm[idx] = __float2half_rn(v);
    }
    __syncthreads();

    const int wid  = t >> 5;
    const int lane = t & 31;

    for (int row = blockIdx.x * 8 + wid; row < BB; row += gridDim.x * 8) {
        const uint4* xc4 = (const uint4*)(g_xch + (size_t)row * 1024);
        const uint4* xx4 = (const uint4*)(g_xh  + (size_t)row * 1024);
        float xcf[32], xxf[32];
#pragma unroll
        for (int j = 0; j < 4; j++) {
            uint4 vc = xc4[lane + j * 32];
            uint4 vx = xx4[lane + j * 32];
            const __half2* hc = (const __half2*)&vc;
            const __half2* hx = (const __half2*)&vx;
#pragma unroll
            for (int q = 0; q < 4; q++) {
                float2 fc = __half22float2(hc[q]);
                float2 fx = __half22float2(hx[q]);
                xcf[j * 8 + q * 2]     = fc.x; xcf[j * 8 + q * 2 + 1] = fc.y;
                xxf[j * 8 + q * 2]     = fx.x; xxf[j * 8 + q * 2 + 1] = fx.y;
            }
        }
#pragma unroll 1
        for (int gg = 0; gg < 24; gg++) {
            const uint4* w4 = (const uint4*)(wsm + gg * 1024);
            const float* xf = (gg < 16) ? xcf : xxf;
            float acc = 0.0f;
#pragma unroll
            for (int j = 0; j < 4; j++) {
                uint4 wv = w4[lane + j * 32];
                const __half2* hw = (const __half2*)&wv;
#pragma unroll
                for (int q = 0; q < 4; q++) {
                    float2 fw2 = __half22float2(hw[q]);
                    acc += xf[j * 8 + q * 2] * fw2.x + xf[j * 8 + q * 2 + 1] * fw2.y;
                }
            }
#pragma unroll
            for (int off = 16; off > 0; off >>= 1)
                acc += __shfl_xor_sync(0xffffffffu, acc, off);
            if (lane == 0) {
                if (gg < 8)       g_it[row * 8 + gg]        = softcapf(acc + ib[gg]);
                else if (gg < 16) g_ft[row * 8 + gg - 8]    = softcapf(acc + fb[gg - 8]);
                else {
                    float vo = softcapf(acc + ob[gg - 16]);
                    g_og[row * 8 + gg - 16] = 1.0f / (1.0f + expf(-vo));
                }
            }
        }
    }
}

// ---------------- launch --------------------------------------------------------
extern "C" void kernel_launch(void* const* d_in, const int* in_sizes, int n_in,
                              void* d_out, int out_size) {
    const float* x      = (const float*)d_in[0];
    const float* c      = (const float*)d_in[1];
    const float* n      = (const float*)d_in[2];
    const float* m      = (const float*)d_in[3];
    const float* conv_w = (const float*)d_in[4];
    const float* conv_b = (const float*)d_in[5];
    const float* z_w    = (const float*)d_in[6];
    const float* i_w    = (const float*)d_in[7];
    const float* i_b    = (const float*)d_in[8];
    const float* f_w    = (const float*)d_in[9];
    const float* f_b    = (const float*)d_in[10];
    const float* o_w    = (const float*)d_in[11];
    const float* o_b    = (const float*)d_in[12];
    const float* gn_w   = (const float*)d_in[13];
    const float* gn_b   = (const float*)d_in[14];
    const float* out_w  = (const float*)d_in[15];

    float* out   = (float*)d_out;
    float* c_out = out   + (size_t)BB * DD;
    float* n_out = c_out + (size_t)BB * DD;
    float* m_out = n_out + (size_t)BB * DD;

    __half *p_xh, *p_xch, *p_hh, *p_wchi, *p_wzhi, *p_wohi;
    cudaGetSymbolAddress((void**)&p_xh,   g_xh);
    cudaGetSymbolAddress((void**)&p_xch,  g_xch);
    cudaGetSymbolAddress((void**)&p_hh,   g_hh);
    cudaGetSymbolAddress((void**)&p_wchi, g_wc_hi);
    cudaGetSymbolAddress((void**)&p_wzhi, g_wz_hi);
    cudaGetSymbolAddress((void**)&p_wohi, g_wo_hi);

    cudaFuncSetAttribute((const void*)gemm2_kernel<1, 1>, cudaFuncAttributeMaxDynamicSharedMemorySize, GEMM_SMEM);
    cudaFuncSetAttribute((const void*)gemm2_kernel<2, 1>, cudaFuncAttributeMaxDynamicSharedMemorySize, GEMM_SMEM);
    cudaFuncSetAttribute((const void*)gemm2_kernel<0, 1>, cudaFuncAttributeMaxDynamicSharedMemorySize, GEMM_SMEM);

    tohalf_kernel<<<(BB * DD / 8 + 255) / 256, 256>>>(x, p_xh, BB * DD / 8);
    wconv_kernel<<<(DD * DD + 255) / 256, 256>>>(conv_w);
    tohalf_kernel<<<(DD * DD / 8 + 255) / 256, 256>>>(z_w,   p_wzhi, DD * DD / 8);
    tohalf_kernel<<<(DD * DD / 8 + 255) / 256, 256>>>(out_w, p_wohi, DD * DD / 8);

    dim3 gg(DD / 128, BB / 128);   // (8, 256)

    // conv GEMM (1-term) -> SiLU -> fp16 xconv
    gemm2_kernel<1, 1><<<gg, 256, GEMM_SMEM>>>(
        p_xh, p_wchi, nullptr, conv_b, p_xch,
        nullptr, nullptr, nullptr, nullptr, nullptr, nullptr, nullptr, nullptr);
    // gate projections
    gates_kernel<<<592, 256>>>(i_b, f_b, o_b, i_w, f_w, o_w);
    // z GEMM (1-term) + fused gating/LayerNorm epilogue
    gemm2_kernel<2, 1><<<gg, 256, GEMM_SMEM>>>(
        p_xh, p_wzhi, nullptr, nullptr, nullptr,
        c, n, m, gn_w, gn_b, c_out, n_out, m_out);
    // out projection (1-term) -> fp32
    gemm2_kernel<0, 1><<<gg, 256, GEMM_SMEM>>>(
        p_hh, p_wohi, nullptr, nullptr, out,
        nullptr, nullptr, nullptr, nullptr, nullptr, nullptr, nullptr, nullptr);
}

// round 14
// speedup vs baseline: 1.4813x; 1.0056x over previous
#include <cuda_runtime.h>
#include <cuda_fp16.h>
#include <math.h>
#include <stdint.h>

#define BB   32768
#define DD   1024
#define NHEAD 8
#define KTAP 4
#define EPSV 1e-6f
#define CAPV 15.0f

// ---------------- scratch (allocation-free, __device__ globals) ----------------
__device__ __half g_xh[(size_t)BB * DD];     // x as fp16
__device__ __half g_xch[(size_t)BB * DD];    // SiLU(conv tap) as fp16
__device__ __half g_hh[(size_t)BB * DD];     // h_norm as fp16
__device__ __half g_wc_hi[DD * DD];          // conv last tap
__device__ __half g_wz_hi[DD * DD];          // z_w
__device__ __half g_wo_hi[DD * DD];          // out_w
__device__ float g_it[BB * NHEAD];
__device__ float g_ft[BB * NHEAD];
__device__ float g_og[BB * NHEAD];

// ================= low-level helpers (arch-portable, sm_80+) ===================
__device__ __forceinline__ uint32_t smem_u32(const void* p) {
    uint32_t a;
    asm("{ .reg .u64 t; cvta.to.shared.u64 t, %1; cvt.u32.u64 %0, t; }" : "=r"(a) : "l"(p));
    return a;
}
__device__ __forceinline__ void cp16(uint32_t dst, const void* src) {
    asm volatile("cp.async.cg.shared.global [%0], [%1], 16;" :: "r"(dst), "l"(src));
}
__device__ __forceinline__ void cp_commit() {
    asm volatile("cp.async.commit_group;" ::: "memory");
}
__device__ __forceinline__ void cp_wait0() {
    asm volatile("cp.async.wait_group 0;" ::: "memory");
}
__device__ __forceinline__ void ldsm4(uint32_t* r, uint32_t addr) {
    asm volatile("ldmatrix.sync.aligned.m8n8.x4.shared.b16 {%0,%1,%2,%3}, [%4];"
                 : "=r"(r[0]), "=r"(r[1]), "=r"(r[2]), "=r"(r[3]) : "r"(addr));
}
__device__ __forceinline__ void mma_f16(float* d, const uint32_t* a, const uint32_t* b) {
    asm volatile(
        "mma.sync.aligned.m16n8k16.row.col.f32.f16.f16.f32 "
        "{%0,%1,%2,%3}, {%4,%5,%6,%7}, {%8,%9}, {%0,%1,%2,%3};"
        : "+f"(d[0]), "+f"(d[1]), "+f"(d[2]), "+f"(d[3])
        : "r"(a[0]), "r"(a[1]), "r"(a[2]), "r"(a[3]), "r"(b[0]), "r"(b[1]));
}

// ================= conversion kernels ==========================================
__global__ void tohalf_kernel(const float* __restrict__ in, __half* __restrict__ out, int n8) {
    int i = blockIdx.x * blockDim.x + threadIdx.x;
    if (i >= n8) return;
    float4 a = ((const float4*)in)[i * 2];
    float4 b = ((const float4*)in)[i * 2 + 1];
    __half2 h[4];
    h[0] = __floats2half2_rn(a.x, a.y);
    h[1] = __floats2half2_rn(a.z, a.w);
    h[2] = __floats2half2_rn(b.x, b.y);
    h[3] = __floats2half2_rn(b.z, b.w);
    ((uint4*)out)[i] = *(uint4*)h;
}

__global__ void wconv_kernel(const float* __restrict__ conv_w) {
    int i = blockIdx.x * blockDim.x + threadIdx.x;
    if (i >= DD * DD) return;
    g_wc_hi[i] = __float2half_rn(conv_w[(size_t)i * KTAP + (KTAP - 1)]);
}

// ================= tensor-core GEMM =============================================
// C[M,1024] = A[M,1024] * W[1024,1024]^T, fp16 operands, fp32 accum.
// Block 128x128, BK=64, 2 stages, one barrier per k-iter, 2 CTAs/SM.
// Register-level fragment double-buffering across k16 steps.
// MODE 0: fp32 out. MODE 1: SiLU(y+bias) -> fp16 out.
// MODE 2: fused sLSTM gating + per-head LayerNorm epilogue (tile = one head).
// Stage layout pinned identical to the round-10/13 artifact (2 CTAs/SM).
#define TSTRIDE   144                     // 128B data + 16B pad (conflict-free)
#define TENSOR_B  (128 * TSTRIDE)         // 18432
#define STAGE_B   (3 * TENSOR_B)          // 3 slots (3rd unused, pins occupancy)
#define NSTAGE    2
#define GEMM_SMEM (NSTAGE * STAGE_B)      // 110592 -> exactly 2 CTAs/SM

template <int MODE>
__global__ void __launch_bounds__(256, 2)
gemm2_kernel(const __half* __restrict__ Ah, const __half* __restrict__ Whi,
             const float* __restrict__ bias, void* __restrict__ Cout,
             const float* __restrict__ cc, const float* __restrict__ nn_,
             const float* __restrict__ mm_,
             const float* __restrict__ gw, const float* __restrict__ gb,
             float* __restrict__ c_out, float* __restrict__ n_out,
             float* __restrict__ m_out) {
    extern __shared__ char dynsmem[];
    const uint32_t sbase = smem_u32(dynsmem);

    const int t      = threadIdx.x;
    const int lane   = t & 31;
    const int wid    = t >> 5;
    const int warp_m = wid >> 2;
    const int warp_n = wid & 3;
    const int m0     = blockIdx.y * 128;
    const int n0     = blockIdx.x * 128;

    const char* srcs[2];
    srcs[0] = (const char*)(Ah  + (size_t)m0 * DD);
    srcs[1] = (const char*)(Whi + (size_t)n0 * DD);

    // 2048 16B chunks per stage (2 tensors x 128 rows x 8 chunks), 8 per thread
    int l_tensor[8], l_row[8], l_ch[8];
#pragma unroll
    for (int j = 0; j < 8; j++) {
        int cid = t + j * 256;
        l_tensor[j] = cid >> 10;
        int rc = cid & 1023;
        l_row[j] = rc >> 3;
        l_ch[j]  = rc & 7;
    }

    auto load_stage = [&](int stg, int kiter) {
        uint32_t sdst = sbase + stg * STAGE_B;
        int k0b = kiter * 128;                // 64 fp16 = 128B along K
#pragma unroll
        for (int j = 0; j < 8; j++) {
            uint32_t dst = sdst + l_tensor[j] * TENSOR_B + l_row[j] * TSTRIDE + l_ch[j] * 16;
            const char* src = srcs[l_tensor[j]] + (size_t)l_row[j] * 2048 + k0b + l_ch[j] * 16;
            cp16(dst, src);
        }
    };

    float acc[4][4][4];
#pragma unroll
    for (int i = 0; i < 4; i++)
#pragma unroll
        for (int j = 0; j < 4; j++)
#pragma unroll
            for (int q = 0; q < 4; q++) acc[i][j][q] = 0.0f;

    const uint32_t offA = (uint32_t)((warp_m * 64 + (lane & 15)) * TSTRIDE + (lane >> 4) * 16);
    const uint32_t offB = (uint32_t)((warp_n * 32 + ((lane >> 4) << 3) + (lane & 7)) * TSTRIDE
                        + (((lane >> 3) & 1) << 4));

    load_stage(0, 0);
    cp_commit();

    uint32_t ah[2][4][4], bh[2][2][4];

    for (int i = 0; i < 16; i++) {
        cp_wait0();
        __syncthreads();
        if (i + 1 < 16) {
            load_stage((i + 1) & 1, i + 1);
            cp_commit();
        }
        const uint32_t stg = sbase + (i & 1) * STAGE_B;

        // prologue: fragments for k16 = 0
#pragma unroll
        for (int p = 0; p < 2; p++)
            ldsm4(bh[0][p], stg + TENSOR_B + offB + p * (16 * TSTRIDE));
#pragma unroll
        for (int mt = 0; mt < 4; mt++)
            ldsm4(ah[0][mt], stg + offA + mt * (16 * TSTRIDE));

#pragma unroll
        for (int k16 = 0; k16 < 4; k16++) {
            const int cur = k16 & 1;
            const int nxt = cur ^ 1;
            if (k16 < 3) {               // prefetch k16+1 while computing k16
                const uint32_t koff = (k16 + 1) * 32;
#pragma unroll
                for (int p = 0; p < 2; p++)
                    ldsm4(bh[nxt][p], stg + TENSOR_B + offB + p * (16 * TSTRIDE) + koff);
#pragma unroll
                for (int mt = 0; mt < 4; mt++)
                    ldsm4(ah[nxt][mt], stg + offA + mt * (16 * TSTRIDE) + koff);
            }
#pragma unroll
            for (int mt = 0; mt < 4; mt++)
#pragma unroll
                for (int nt = 0; nt < 4; nt++)
                    mma_f16(acc[mt][nt], ah[cur][mt], &bh[cur][nt >> 1][(nt & 1) * 2]);
        }
    }

    const int g  = lane >> 2;
    const int tg = lane & 3;

    if (MODE == 2) {
        // ======== fused gating + per-head LayerNorm epilogue ====================
        const int hidx = blockIdx.x;   // tile n-range == head hidx
        float* ep    = (float*)dynsmem;
        float* sig   = ep;            // [128] i gate (exp)
        float* sfg   = ep + 128;      // [128] f gate (exp)
        float* sog   = ep + 256;      // [128] o gate (sigmoid)
        float* gwsm  = ep + 384;      // [128]
        float* gbsm  = ep + 512;      // [128]
        float* rsum  = ep + 640;      // [4][128]
        float* rsq   = ep + 1152;     // [4][128]

        __syncthreads();              // mainloop smem dead
        if (t < 128) {
            int bh_i = (m0 + t) * 8 + hidx;
            float it  = g_it[bh_i];
            float ft  = g_ft[bh_i];
            float m0v = mm_[bh_i];
            float fl  = -log1pf(expf(-ft));
            float mn  = fmaxf(fl + m0v, it);
            sig[t] = expf(it - mn);
            sfg[t] = expf(fl + m0v - mn);
            sog[t] = g_og[bh_i];
            m_out[bh_i] = mn;
        } else {
            int e = t - 128;
            gwsm[e] = gw[hidx * 128 + e];
            gbsm[e] = gb[hidx * 128 + e];
        }
        __syncthreads();

        // phase 1: c_new/n_new, h, partial row sums
#pragma unroll
        for (int mt = 0; mt < 4; mt++) {
#pragma unroll
            for (int hf = 0; hf < 2; hf++) {
                int r = warp_m * 64 + mt * 16 + g + hf * 8;
                float igv = sig[r], fgv = sfg[r], ogv = sog[r];
                size_t rowbase = (size_t)(m0 + r) * 1024 + hidx * 128;
                float s = 0.f, sq = 0.f;
#pragma unroll
                for (int nt = 0; nt < 4; nt++) {
                    int e = warp_n * 32 + nt * 8 + tg * 2;
                    float2 cv = *(const float2*)&cc[rowbase + e];
                    float2 nv = *(const float2*)&nn_[rowbase + e];
                    float z0 = acc[mt][nt][hf * 2 + 0];
                    float z1 = acc[mt][nt][hf * 2 + 1];
                    float cn0 = fgv * cv.x + igv * z0;
                    float cn1 = fgv * cv.y + igv * z1;
                    float nn0 = fgv * nv.x + igv;
                    float nn1 = fgv * nv.y + igv;
                    *(float2*)&c_out[rowbase + e] = make_float2(cn0, cn1);
                    *(float2*)&n_out[rowbase + e] = make_float2(nn0, nn1);
                    float h0 = ogv * cn0 / (nn0 + EPSV);
                    float h1 = ogv * cn1 / (nn1 + EPSV);
                    acc[mt][nt][hf * 2 + 0] = h0;
                    acc[mt][nt][hf * 2 + 1] = h1;
                    s += h0 + h1;
                    sq += h0 * h0 + h1 * h1;
                }
                s  += __shfl_xor_sync(0xffffffffu, s, 1);
                s  += __shfl_xor_sync(0xffffffffu, s, 2);
                sq += __shfl_xor_sync(0xffffffffu, sq, 1);
                sq += __shfl_xor_sync(0xffffffffu, sq, 2);
                if (tg == 0) {
                    rsum[warp_n * 128 + r] = s;
                    rsq[warp_n * 128 + r]  = sq;
                }
            }
        }
        __syncthreads();

        // phase 2: normalize + affine -> fp16 h
#pragma unroll
        for (int mt = 0; mt < 4; mt++) {
#pragma unroll
            for (int hf = 0; hf < 2; hf++) {
                int r = warp_m * 64 + mt * 16 + g + hf * 8;
                float s  = rsum[r] + rsum[128 + r] + rsum[256 + r] + rsum[384 + r];
                float sq = rsq[r]  + rsq[128 + r]  + rsq[256 + r]  + rsq[384 + r];
                float mu  = s * (1.0f / 128.0f);
                float var = sq * (1.0f / 128.0f) - mu * mu;
                float rs  = rsqrtf(var + EPSV);
                size_t rowbase = (size_t)(m0 + r) * 1024 + hidx * 128;
#pragma unroll
                for (int nt = 0; nt < 4; nt++) {
                    int e = warp_n * 32 + nt * 8 + tg * 2;
                    float h0 = (acc[mt][nt][hf * 2 + 0] - mu) * rs * gwsm[e]     + gbsm[e];
                    float h1 = (acc[mt][nt][hf * 2 + 1] - mu) * rs * gwsm[e + 1] + gbsm[e + 1];
                    *(__half2*)&g_hh[rowbase + e] = __floats2half2_rn(h0, h1);
                }
            }
        }
    } else {
        // ======== plain / SiLU epilogue =========================================
#pragma unroll
        for (int mt = 0; mt < 4; mt++) {
#pragma unroll
            for (int nt = 0; nt < 4; nt++) {
                int col  = n0 + warp_n * 32 + nt * 8 + tg * 2;
                int rowa = m0 + warp_m * 64 + mt * 16 + g;
                float2 v0, v1;
                v0.x = acc[mt][nt][0]; v0.y = acc[mt][nt][1];
                v1.x = acc[mt][nt][2]; v1.y = acc[mt][nt][3];
                if (MODE == 1) {
                    float b0 = bias[col], b1 = bias[col + 1];
                    v0.x += b0; v0.y += b1; v1.x += b0; v1.y += b1;
                    v0.x = v0.x / (1.0f + expf(-v0.x));
                    v0.y = v0.y / (1.0f + expf(-v0.y));
                    v1.x = v1.x / (1.0f + expf(-v1.x));
                    v1.y = v1.y / (1.0f + expf(-v1.y));
                    __half* C = (__half*)Cout;
                    *(__half2*)&C[(size_t)rowa * DD + col]       = __floats2half2_rn(v0.x, v0.y);
                    *(__half2*)&C[(size_t)(rowa + 8) * DD + col] = __floats2half2_rn(v1.x, v1.y);
                } else {
                    float* C = (float*)Cout;
                    *(float2*)&C[(size_t)rowa * DD + col]       = v0;
                    *(float2*)&C[(size_t)(rowa + 8) * DD + col] = v1;
                }
            }
        }
    }
}

// ---------------- gates: i,f from xconv(fp16); o from x(fp16); smem weights ----
__device__ __forceinline__ float softcapf(float x) {
    return CAPV * tanhf(x * (1.0f / CAPV));
}

__global__ void __launch_bounds__(256)
gates_kernel(const float* __restrict__ ib, const float* __restrict__ fb,
             const float* __restrict__ ob,
             const float* __restrict__ iw, const float* __restrict__ fw,
             const float* __restrict__ ow) {
    __shared__ __half wsm[24 * 1024];      // 48KB: i0-7, f0-7, o0-7

    const int t = threadIdx.x;
    for (int idx = t; idx < 24 * 1024; idx += 256) {
        int gg = idx >> 10, k = idx & 1023;
        float v = (gg < 8) ? iw[gg * 1024 + k]
                : (gg < 16) ? fw[(gg - 8) * 1024 + k]
                            : ow[(gg - 16) * 1024 + k];
        wsm[idx] = __float2half_rn(v);
    }
    __syncthreads();

    const int wid  = t >> 5;
    const int lane = t & 31;

    for (int row = blockIdx.x * 8 + wid; row < BB; row += gridDim.x * 8) {
        const uint4* xc4 = (const uint4*)(g_xch + (size_t)row * 1024);
        const uint4* xx4 = (const uint4*)(g_xh  + (size_t)row * 1024);
        float xcf[32], xxf[32];
#pragma unroll
        for (int j = 0; j < 4; j++) {
            uint4 vc = xc4[lane + j * 32];
            uint4 vx = xx4[lane + j * 32];
            const __half2* hc = (const __half2*)&vc;
            const __half2* hx = (const __half2*)&vx;
#pragma unroll
            for (int q = 0; q < 4; q++) {
                float2 fc = __half22float2(hc[q]);
                float2 fx = __half22float2(hx[q]);
                xcf[j * 8 + q * 2]     = fc.x; xcf[j * 8 + q * 2 + 1] = fc.y;
                xxf[j * 8 + q * 2]     = fx.x; xxf[j * 8 + q * 2 + 1] = fx.y;
            }
        }
#pragma unroll 1
        for (int gg = 0; gg < 24; gg++) {
            const uint4* w4 = (const uint4*)(wsm + gg * 1024);
            const float* xf = (gg < 16) ? xcf : xxf;
            float acc = 0.0f;
#pragma unroll
            for (int j = 0; j < 4; j++) {
                uint4 wv = w4[lane + j * 32];
                const __half2* hw = (const __half2*)&wv;
#pragma unroll
                for (int q = 0; q < 4; q++) {
                    float2 fw2 = __half22float2(hw[q]);
                    acc += xf[j * 8 + q * 2] * fw2.x + xf[j * 8 + q * 2 + 1] * fw2.y;
                }
            }
#pragma unroll
            for (int off = 16; off > 0; off >>= 1)
                acc += __shfl_xor_sync(0xffffffffu, acc, off);
            if (lane == 0) {
                if (gg < 8)       g_it[row * 8 + gg]        = softcapf(acc + ib[gg]);
                else if (gg < 16) g_ft[row * 8 + gg - 8]    = softcapf(acc + fb[gg - 8]);
                else {
                    float vo = softcapf(acc + ob[gg - 16]);
                    g_og[row * 8 + gg - 16] = 1.0f / (1.0f + expf(-vo));
                }
            }
        }
    }
}

// ---------------- launch --------------------------------------------------------
extern "C" void kernel_launch(void* const* d_in, const int* in_sizes, int n_in,
                              void* d_out, int out_size) {
    const float* x      = (const float*)d_in[0];
    const float* c      = (const float*)d_in[1];
    const float* n      = (const float*)d_in[2];
    const float* m      = (const float*)d_in[3];
    const float* conv_w = (const float*)d_in[4];
    const float* conv_b = (const float*)d_in[5];
    const float* z_w    = (const float*)d_in[6];
    const float* i_w    = (const float*)d_in[7];
    const float* i_b    = (const float*)d_in[8];
    const float* f_w    = (const float*)d_in[9];
    const float* f_b    = (const float*)d_in[10];
    const float* o_w    = (const float*)d_in[11];
    const float* o_b    = (const float*)d_in[12];
    const float* gn_w   = (const float*)d_in[13];
    const float* gn_b   = (const float*)d_in[14];
    const float* out_w  = (const float*)d_in[15];

    float* out   = (float*)d_out;
    float* c_out = out   + (size_t)BB * DD;
    float* n_out = c_out + (size_t)BB * DD;
    float* m_out = n_out + (size_t)BB * DD;

    __half *p_xh, *p_xch, *p_hh, *p_wchi, *p_wzhi, *p_wohi;
    cudaGetSymbolAddress((void**)&p_xh,   g_xh);
    cudaGetSymbolAddress((void**)&p_xch,  g_xch);
    cudaGetSymbolAddress((void**)&p_hh,   g_hh);
    cudaGetSymbolAddress((void**)&p_wchi, g_wc_hi);
    cudaGetSymbolAddress((void**)&p_wzhi, g_wz_hi);
    cudaGetSymbolAddress((void**)&p_wohi, g_wo_hi);

    cudaFuncSetAttribute((const void*)gemm2_kernel<0>, cudaFuncAttributeMaxDynamicSharedMemorySize, GEMM_SMEM);
    cudaFuncSetAttribute((const void*)gemm2_kernel<1>, cudaFuncAttributeMaxDynamicSharedMemorySize, GEMM_SMEM);
    cudaFuncSetAttribute((const void*)gemm2_kernel<2>, cudaFuncAttributeMaxDynamicSharedMemorySize, GEMM_SMEM);

    tohalf_kernel<<<(BB * DD / 8 + 255) / 256, 256>>>(x, p_xh, BB * DD / 8);
    wconv_kernel<<<(DD * DD + 255) / 256, 256>>>(conv_w);
    tohalf_kernel<<<(DD * DD / 8 + 255) / 256, 256>>>(z_w,   p_wzhi, DD * DD / 8);
    tohalf_kernel<<<(DD * DD / 8 + 255) / 256, 256>>>(out_w, p_wohi, DD * DD / 8);

    dim3 gg(DD / 128, BB / 128);   // (8, 256)

    // conv GEMM -> SiLU -> fp16 xconv
    gemm2_kernel<1><<<gg, 256, GEMM_SMEM>>>(
        p_xh, p_wchi, conv_b, p_xch,
        nullptr, nullptr, nullptr, nullptr, nullptr, nullptr, nullptr, nullptr);
    // gate projections
    gates_kernel<<<592, 256>>>(i_b, f_b, o_b, i_w, f_w, o_w);
    // z GEMM + fused gating/LayerNorm epilogue
    gemm2_kernel<2><<<gg, 256, GEMM_SMEM>>>(
        p_xh, p_wzhi, nullptr, nullptr,
        c, n, m, gn_w, gn_b, c_out, n_out, m_out);
    // out projection -> fp32
    gemm2_kernel<0><<<gg, 256, GEMM_SMEM>>>(
        p_hh, p_wohi, nullptr, out,
        nullptr, nullptr, nullptr, nullptr, nullptr, nullptr, nullptr, nullptr);
}

// round 15
// speedup vs baseline: 1.7474x; 1.1797x over previous
#include <cuda_runtime.h>
#include <cuda_fp16.h>
#include <math.h>
#include <stdint.h>

#define BB   32768
#define DD   1024
#define NHEAD 8
#define KTAP 4
#define EPSV 1e-6f
#define CAPV 15.0f

// ---------------- scratch (allocation-free, __device__ globals) ----------------
__device__ __half g_xh[(size_t)BB * DD];     // x as fp16
__device__ __half g_hh[(size_t)BB * DD];     // h_norm as fp16
__device__ __half g_wc_hi[DD * DD];          // conv last tap
__device__ __half g_wz_hi[DD * DD];          // z_w
__device__ __half g_wo_hi[DD * DD];          // out_w
__device__ float g_Pp[16 * 8 * BB];          // i/f gate partials [gate16][bx8][row]
__device__ float g_it[BB * NHEAD];
__device__ float g_ft[BB * NHEAD];
__device__ float g_og[BB * NHEAD];

// ================= low-level helpers (arch-portable, sm_80+) ===================
__device__ __forceinline__ uint32_t smem_u32(const void* p) {
    uint32_t a;
    asm("{ .reg .u64 t; cvta.to.shared.u64 t, %1; cvt.u32.u64 %0, t; }" : "=r"(a) : "l"(p));
    return a;
}
__device__ __forceinline__ void cp16(uint32_t dst, const void* src) {
    asm volatile("cp.async.cg.shared.global [%0], [%1], 16;" :: "r"(dst), "l"(src));
}
__device__ __forceinline__ void cp_commit() {
    asm volatile("cp.async.commit_group;" ::: "memory");
}
__device__ __forceinline__ void cp_wait0() {
    asm volatile("cp.async.wait_group 0;" ::: "memory");
}
__device__ __forceinline__ void ldsm4(uint32_t* r, uint32_t addr) {
    asm volatile("ldmatrix.sync.aligned.m8n8.x4.shared.b16 {%0,%1,%2,%3}, [%4];"
                 : "=r"(r[0]), "=r"(r[1]), "=r"(r[2]), "=r"(r[3]) : "r"(addr));
}
__device__ __forceinline__ void mma_f16(float* d, const uint32_t* a, const uint32_t* b) {
    asm volatile(
        "mma.sync.aligned.m16n8k16.row.col.f32.f16.f16.f32 "
        "{%0,%1,%2,%3}, {%4,%5,%6,%7}, {%8,%9}, {%0,%1,%2,%3};"
        : "+f"(d[0]), "+f"(d[1]), "+f"(d[2]), "+f"(d[3])
        : "r"(a[0]), "r"(a[1]), "r"(a[2]), "r"(a[3]), "r"(b[0]), "r"(b[1]));
}
__device__ __forceinline__ float softcapf(float x) {
    return CAPV * tanhf(x * (1.0f / CAPV));
}

// ================= conversion kernels ==========================================
__global__ void tohalf_kernel(const float* __restrict__ in, __half* __restrict__ out, int n8) {
    int i = blockIdx.x * blockDim.x + threadIdx.x;
    if (i >= n8) return;
    float4 a = ((const float4*)in)[i * 2];
    float4 b = ((const float4*)in)[i * 2 + 1];
    __half2 h[4];
    h[0] = __floats2half2_rn(a.x, a.y);
    h[1] = __floats2half2_rn(a.z, a.w);
    h[2] = __floats2half2_rn(b.x, b.y);
    h[3] = __floats2half2_rn(b.z, b.w);
    ((uint4*)out)[i] = *(uint4*)h;
}

__global__ void wconv_kernel(const float* __restrict__ conv_w) {
    int i = blockIdx.x * blockDim.x + threadIdx.x;
    if (i >= DD * DD) return;
    g_wc_hi[i] = __float2half_rn(conv_w[(size_t)i * KTAP + (KTAP - 1)]);
}

// ================= tensor-core GEMM =============================================
// C[M,1024] = A[M,1024] * W[1024,1024]^T, fp16 operands, fp32 accum.
// Block 128x128, BK=64, 2 stages, one barrier per k-iter, 2 CTAs/SM.
// MODE 0: fp32 out.
// MODE 2: fused sLSTM gating + per-head LayerNorm epilogue (tile = one head).
// MODE 3: conv: SiLU(y+bias) kept in regs; i/f gate partial dots -> g_Pp. No C.
#define TSTRIDE   144                     // 128B data + 16B pad (conflict-free)
#define TENSOR_B  (128 * TSTRIDE)         // 18432
#define STAGE_B   (3 * TENSOR_B)          // 3 slots (3rd unused, pins occupancy)
#define NSTAGE    2
#define GEMM_SMEM (NSTAGE * STAGE_B)      // 110592 -> exactly 2 CTAs/SM

template <int MODE>
__global__ void __launch_bounds__(256, 2)
gemm2_kernel(const __half* __restrict__ Ah, const __half* __restrict__ Whi,
             const float* __restrict__ bias, void* __restrict__ Cout,
             const float* __restrict__ cc, const float* __restrict__ nn_,
             const float* __restrict__ mm_,
             const float* __restrict__ gw, const float* __restrict__ gb,
             float* __restrict__ c_out, float* __restrict__ n_out,
             float* __restrict__ m_out) {
    extern __shared__ char dynsmem[];
    const uint32_t sbase = smem_u32(dynsmem);

    const int t      = threadIdx.x;
    const int lane   = t & 31;
    const int wid    = t >> 5;
    const int warp_m = wid >> 2;
    const int warp_n = wid & 3;
    const int m0     = blockIdx.y * 128;
    const int n0     = blockIdx.x * 128;

    const char* srcs[2];
    srcs[0] = (const char*)(Ah  + (size_t)m0 * DD);
    srcs[1] = (const char*)(Whi + (size_t)n0 * DD);

    int l_tensor[8], l_row[8], l_ch[8];
#pragma unroll
    for (int j = 0; j < 8; j++) {
        int cid = t + j * 256;
        l_tensor[j] = cid >> 10;
        int rc = cid & 1023;
        l_row[j] = rc >> 3;
        l_ch[j]  = rc & 7;
    }

    auto load_stage = [&](int stg, int kiter) {
        uint32_t sdst = sbase + stg * STAGE_B;
        int k0b = kiter * 128;
#pragma unroll
        for (int j = 0; j < 8; j++) {
            uint32_t dst = sdst + l_tensor[j] * TENSOR_B + l_row[j] * TSTRIDE + l_ch[j] * 16;
            const char* src = srcs[l_tensor[j]] + (size_t)l_row[j] * 2048 + k0b + l_ch[j] * 16;
            cp16(dst, src);
        }
    };

    float acc[4][4][4];
#pragma unroll
    for (int i = 0; i < 4; i++)
#pragma unroll
        for (int j = 0; j < 4; j++)
#pragma unroll
            for (int q = 0; q < 4; q++) acc[i][j][q] = 0.0f;

    const uint32_t offA = (uint32_t)((warp_m * 64 + (lane & 15)) * TSTRIDE + (lane >> 4) * 16);
    const uint32_t offB = (uint32_t)((warp_n * 32 + ((lane >> 4) << 3) + (lane & 7)) * TSTRIDE
                        + (((lane >> 3) & 1) << 4));

    load_stage(0, 0);
    cp_commit();

    for (int i = 0; i < 16; i++) {
        cp_wait0();
        __syncthreads();
        if (i + 1 < 16) {
            load_stage((i + 1) & 1, i + 1);
            cp_commit();
        }
        const uint32_t stg = sbase + (i & 1) * STAGE_B;
#pragma unroll
        for (int k16 = 0; k16 < 4; k16++) {
            const uint32_t koff = k16 * 32;
            uint32_t bh[2][4];
#pragma unroll
            for (int p = 0; p < 2; p++)
                ldsm4(bh[p], stg + TENSOR_B + offB + p * (16 * TSTRIDE) + koff);
#pragma unroll
            for (int mt = 0; mt < 4; mt++) {
                uint32_t ah[4];
                ldsm4(ah, stg + offA + mt * (16 * TSTRIDE) + koff);
#pragma unroll
                for (int nt = 0; nt < 4; nt++)
                    mma_f16(acc[mt][nt], ah, &bh[nt >> 1][(nt & 1) * 2]);
            }
        }
    }

    const int g  = lane >> 2;
    const int tg = lane & 3;

    if (MODE == 3) {
        // ======== conv epilogue: SiLU in regs, i/f gate partial dots ============
        // bias + SiLU
#pragma unroll
        for (int mt = 0; mt < 4; mt++)
#pragma unroll
            for (int nt = 0; nt < 4; nt++)
#pragma unroll
                for (int q = 0; q < 4; q++) {
                    int col = n0 + warp_n * 32 + nt * 8 + tg * 2 + (q & 1);
                    float v = acc[mt][nt][q] + bias[col];
                    acc[mt][nt][q] = v / (1.0f + expf(-v));
                }

        float* wg = (float*)dynsmem;          // [16][128] gate weights (cols n0..)
        float* pr = wg + 2048;                // [4 warp_n][16][128] partials
        __syncthreads();                      // mainloop smem dead
#pragma unroll
        for (int j = 0; j < 8; j++) {
            int idx = t + j * 256;            // 0..2047
            int gg2 = idx >> 7, col = idx & 127;
            wg[idx] = (gg2 < 8) ? gw[gg2 * 1024 + n0 + col]      // gw = i_w
                                : gb[(gg2 - 8) * 1024 + n0 + col]; // gb = f_w
        }
        __syncthreads();

#pragma unroll 1
        for (int gg2 = 0; gg2 < 16; gg2++) {
            const float* wrow = wg + gg2 * 128 + warp_n * 32;
            float s[8];
#pragma unroll
            for (int mt = 0; mt < 4; mt++)
#pragma unroll
                for (int hf = 0; hf < 2; hf++) {
                    float v = 0.f;
#pragma unroll
                    for (int nt = 0; nt < 4; nt++) {
                        int cl = nt * 8 + tg * 2;
                        v += acc[mt][nt][hf * 2 + 0] * wrow[cl]
                           + acc[mt][nt][hf * 2 + 1] * wrow[cl + 1];
                    }
                    s[mt * 2 + hf] = v;
                }
#pragma unroll
            for (int p = 0; p < 8; p++) {
                s[p] += __shfl_xor_sync(0xffffffffu, s[p], 1);
                s[p] += __shfl_xor_sync(0xffffffffu, s[p], 2);
            }
            if (tg == 0) {
#pragma unroll
                for (int mt = 0; mt < 4; mt++)
#pragma unroll
                    for (int hf = 0; hf < 2; hf++) {
                        int r = warp_m * 64 + mt * 16 + g + hf * 8;
                        pr[warp_n * 2048 + gg2 * 128 + r] = s[mt * 2 + hf];
                    }
            }
        }
        __syncthreads();
        float* Pp = (float*)Cout;             // g_Pp
#pragma unroll
        for (int j = 0; j < 8; j++) {
            int idx = t + j * 256;            // 0..2047 -> (gate, r)
            int gg2 = idx >> 7, r = idx & 127;
            float v = pr[idx] + pr[2048 + idx] + pr[4096 + idx] + pr[6144 + idx];
            Pp[((size_t)gg2 * 8 + blockIdx.x) * BB + m0 + r] = v;
        }
    } else if (MODE == 2) {
        // ======== fused gating + per-head LayerNorm epilogue ====================
        const int hidx = blockIdx.x;
        float* ep    = (float*)dynsmem;
        float* sig   = ep;
        float* sfg   = ep + 128;
        float* sog   = ep + 256;
        float* gwsm  = ep + 384;
        float* gbsm  = ep + 512;
        float* rsum  = ep + 640;
        float* rsq   = ep + 1152;

        __syncthreads();
        if (t < 128) {
            int bh_i = (m0 + t) * 8 + hidx;
            float it  = g_it[bh_i];
            float ft  = g_ft[bh_i];
            float m0v = mm_[bh_i];
            float fl  = -log1pf(expf(-ft));
            float mn  = fmaxf(fl + m0v, it);
            sig[t] = expf(it - mn);
            sfg[t] = expf(fl + m0v - mn);
            sog[t] = g_og[bh_i];
            m_out[bh_i] = mn;
        } else {
            int e = t - 128;
            gwsm[e] = gw[hidx * 128 + e];
            gbsm[e] = gb[hidx * 128 + e];
        }
        __syncthreads();

#pragma unroll
        for (int mt = 0; mt < 4; mt++) {
#pragma unroll
            for (int hf = 0; hf < 2; hf++) {
                int r = warp_m * 64 + mt * 16 + g + hf * 8;
                float igv = sig[r], fgv = sfg[r], ogv = sog[r];
                size_t rowbase = (size_t)(m0 + r) * 1024 + hidx * 128;
                float s = 0.f, sq = 0.f;
#pragma unroll
                for (int nt = 0; nt < 4; nt++) {
                    int e = warp_n * 32 + nt * 8 + tg * 2;
                    float2 cv = *(const float2*)&cc[rowbase + e];
                    float2 nv = *(const float2*)&nn_[rowbase + e];
                    float z0 = acc[mt][nt][hf * 2 + 0];
                    float z1 = acc[mt][nt][hf * 2 + 1];
                    float cn0 = fgv * cv.x + igv * z0;
                    float cn1 = fgv * cv.y + igv * z1;
                    float nn0 = fgv * nv.x + igv;
                    float nn1 = fgv * nv.y + igv;
                    *(float2*)&c_out[rowbase + e] = make_float2(cn0, cn1);
                    *(float2*)&n_out[rowbase + e] = make_float2(nn0, nn1);
                    float h0 = ogv * cn0 / (nn0 + EPSV);
                    float h1 = ogv * cn1 / (nn1 + EPSV);
                    acc[mt][nt][hf * 2 + 0] = h0;
                    acc[mt][nt][hf * 2 + 1] = h1;
                    s += h0 + h1;
                    sq += h0 * h0 + h1 * h1;
                }
                s  += __shfl_xor_sync(0xffffffffu, s, 1);
                s  += __shfl_xor_sync(0xffffffffu, s, 2);
                sq += __shfl_xor_sync(0xffffffffu, sq, 1);
                sq += __shfl_xor_sync(0xffffffffu, sq, 2);
                if (tg == 0) {
                    rsum[warp_n * 128 + r] = s;
                    rsq[warp_n * 128 + r]  = sq;
                }
            }
        }
        __syncthreads();

#pragma unroll
        for (int mt = 0; mt < 4; mt++) {
#pragma unroll
            for (int hf = 0; hf < 2; hf++) {
                int r = warp_m * 64 + mt * 16 + g + hf * 8;
                float s  = rsum[r] + rsum[128 + r] + rsum[256 + r] + rsum[384 + r];
                float sq = rsq[r]  + rsq[128 + r]  + rsq[256 + r]  + rsq[384 + r];
                float mu  = s * (1.0f / 128.0f);
                float var = sq * (1.0f / 128.0f) - mu * mu;
                float rs  = rsqrtf(var + EPSV);
                size_t rowbase = (size_t)(m0 + r) * 1024 + hidx * 128;
#pragma unroll
                for (int nt = 0; nt < 4; nt++) {
                    int e = warp_n * 32 + nt * 8 + tg * 2;
                    float h0 = (acc[mt][nt][hf * 2 + 0] - mu) * rs * gwsm[e]     + gbsm[e];
                    float h1 = (acc[mt][nt][hf * 2 + 1] - mu) * rs * gwsm[e + 1] + gbsm[e + 1];
                    *(__half2*)&g_hh[rowbase + e] = __floats2half2_rn(h0, h1);
                }
            }
        }
    } else {
        // ======== plain fp32 epilogue ===========================================
#pragma unroll
        for (int mt = 0; mt < 4; mt++) {
#pragma unroll
            for (int nt = 0; nt < 4; nt++) {
                int col  = n0 + warp_n * 32 + nt * 8 + tg * 2;
                int rowa = m0 + warp_m * 64 + mt * 16 + g;
                float2 v0, v1;
                v0.x = acc[mt][nt][0]; v0.y = acc[mt][nt][1];
                v1.x = acc[mt][nt][2]; v1.y = acc[mt][nt][3];
                float* C = (float*)Cout;
                *(float2*)&C[(size_t)rowa * DD + col]       = v0;
                *(float2*)&C[(size_t)(rowa + 8) * DD + col] = v1;
            }
        }
    }
}

// ---------------- finalize i/f gates from partials ------------------------------
__global__ void finalize_if_kernel(const float* __restrict__ ib,
                                   const float* __restrict__ fb) {
    int idx = blockIdx.x * 256 + threadIdx.x;     // 0..524287 = gate16 x row
    int gg  = idx >> 15;                          // 0..15
    int row = idx & 32767;
    const float* Pp = g_Pp + (size_t)gg * 8 * BB + row;
    float s = Pp[0] + Pp[(size_t)BB] + Pp[(size_t)2 * BB] + Pp[(size_t)3 * BB]
            + Pp[(size_t)4 * BB] + Pp[(size_t)5 * BB] + Pp[(size_t)6 * BB]
            + Pp[(size_t)7 * BB];
    if (gg < 8) g_it[row * 8 + gg]       = softcapf(s + ib[gg]);
    else        g_ft[row * 8 + (gg - 8)] = softcapf(s + fb[gg - 8]);
}

// ---------------- o gate only: o = sigmoid(softcap(x @ o_w^T + o_b)) ------------
__global__ void __launch_bounds__(256)
gates_o_kernel(const float* __restrict__ ob, const float* __restrict__ ow) {
    __shared__ __half wsm[8 * 1024];      // 16KB

    const int t = threadIdx.x;
    for (int idx = t; idx < 8 * 1024; idx += 256)
        wsm[idx] = __float2half_rn(ow[idx]);
    __syncthreads();

    const int wid  = t >> 5;
    const int lane = t & 31;

    for (int row = blockIdx.x * 8 + wid; row < BB; row += gridDim.x * 8) {
        const uint4* xx4 = (const uint4*)(g_xh + (size_t)row * 1024);
        float xxf[32];
#pragma unroll
        for (int j = 0; j < 4; j++) {
            uint4 vx = xx4[lane + j * 32];
            const __half2* hx = (const __half2*)&vx;
#pragma unroll
            for (int q = 0; q < 4; q++) {
                float2 fx = __half22float2(hx[q]);
                xxf[j * 8 + q * 2]     = fx.x;
                xxf[j * 8 + q * 2 + 1] = fx.y;
            }
        }
#pragma unroll 1
        for (int gg = 0; gg < 8; gg++) {
            const uint4* w4 = (const uint4*)(wsm + gg * 1024);
            float acc = 0.0f;
#pragma unroll
            for (int j = 0; j < 4; j++) {
                uint4 wv = w4[lane + j * 32];
                const __half2* hw = (const __half2*)&wv;
#pragma unroll
                for (int q = 0; q < 4; q++) {
                    float2 fw2 = __half22float2(hw[q]);
                    acc += xxf[j * 8 + q * 2] * fw2.x + xxf[j * 8 + q * 2 + 1] * fw2.y;
                }
            }
#pragma unroll
            for (int off = 16; off > 0; off >>= 1)
                acc += __shfl_xor_sync(0xffffffffu, acc, off);
            if (lane == 0) {
                float vo = softcapf(acc + ob[gg]);
                g_og[row * 8 + gg] = 1.0f / (1.0f + expf(-vo));
            }
        }
    }
}

// ---------------- launch --------------------------------------------------------
extern "C" void kernel_launch(void* const* d_in, const int* in_sizes, int n_in,
                              void* d_out, int out_size) {
    const float* x      = (const float*)d_in[0];
    const float* c      = (const float*)d_in[1];
    const float* n      = (const float*)d_in[2];
    const float* m      = (const float*)d_in[3];
    const float* conv_w = (const float*)d_in[4];
    const float* conv_b = (const float*)d_in[5];
    const float* z_w    = (const float*)d_in[6];
    const float* i_w    = (const float*)d_in[7];
    const float* i_b    = (const float*)d_in[8];
    const float* f_w    = (const float*)d_in[9];
    const float* f_b    = (const float*)d_in[10];
    const float* o_w    = (const float*)d_in[11];
    const float* o_b    = (const float*)d_in[12];
    const float* gn_w   = (const float*)d_in[13];
    const float* gn_b   = (const float*)d_in[14];
    const float* out_w  = (const float*)d_in[15];

    float* out   = (float*)d_out;
    float* c_out = out   + (size_t)BB * DD;
    float* n_out = c_out + (size_t)BB * DD;
    float* m_out = n_out + (size_t)BB * DD;

    __half *p_xh, *p_hh, *p_wchi, *p_wzhi, *p_wohi;
    float  *p_Pp;
    cudaGetSymbolAddress((void**)&p_xh,   g_xh);
    cudaGetSymbolAddress((void**)&p_hh,   g_hh);
    cudaGetSymbolAddress((void**)&p_wchi, g_wc_hi);
    cudaGetSymbolAddress((void**)&p_wzhi, g_wz_hi);
    cudaGetSymbolAddress((void**)&p_wohi, g_wo_hi);
    cudaGetSymbolAddress((void**)&p_Pp,   g_Pp);

    cudaFuncSetAttribute((const void*)gemm2_kernel<0>, cudaFuncAttributeMaxDynamicSharedMemorySize, GEMM_SMEM);
    cudaFuncSetAttribute((const void*)gemm2_kernel<2>, cudaFuncAttributeMaxDynamicSharedMemorySize, GEMM_SMEM);
    cudaFuncSetAttribute((const void*)gemm2_kernel<3>, cudaFuncAttributeMaxDynamicSharedMemorySize, GEMM_SMEM);

    tohalf_kernel<<<(BB * DD / 8 + 255) / 256, 256>>>(x, p_xh, BB * DD / 8);
    wconv_kernel<<<(DD * DD + 255) / 256, 256>>>(conv_w);
    tohalf_kernel<<<(DD * DD / 8 + 255) / 256, 256>>>(z_w,   p_wzhi, DD * DD / 8);
    tohalf_kernel<<<(DD * DD / 8 + 255) / 256, 256>>>(out_w, p_wohi, DD * DD / 8);

    dim3 gg(DD / 128, BB / 128);   // (8, 256)

    // conv GEMM -> SiLU in regs -> i/f gate partials (gw=i_w, gb=f_w, Cout=Pp)
    gemm2_kernel<3><<<gg, 256, GEMM_SMEM>>>(
        p_xh, p_wchi, conv_b, p_Pp,
        nullptr, nullptr, nullptr, i_w, f_w, nullptr, nullptr, nullptr);
    // o gate projection
    gates_o_kernel<<<592, 256>>>(o_b, o_w);
    // finalize i/f gates
    finalize_if_kernel<<<(16 * BB) / 256, 256>>>(i_b, f_b);
    // z GEMM + fused gating/LayerNorm epilogue
    gemm2_kernel<2><<<gg, 256, GEMM_SMEM>>>(
        p_xh, p_wzhi, nullptr, nullptr,
        c, n, m, gn_w, gn_b, c_out, n_out, m_out);
    // out projection -> fp32
    gemm2_kernel<0><<<gg, 256, GEMM_SMEM>>>(
        p_hh, p_wohi, nullptr, out,
        nullptr, nullptr, nullptr, nullptr, nullptr, nullptr, nullptr, nullptr);
}